// round 1
// baseline (speedup 1.0000x reference)
#include <cuda_runtime.h>
#include <math.h>

#define BB   2
#define LL   1024
#define DIMM 768
#define DI   1536
#define DS   16
#define DTR  48
#define NX   80   // DTR + 2*DS

// ---------------- device scratch ----------------
__device__ float g_xz  [2 * BB * LL * 2 * DI];   // per-dir xz (xp | z)
__device__ float g_xc  [2 * BB * LL * DI];       // conv+silu output
__device__ float g_xdbl[2 * BB * LL * NX];       // dt_raw | B | C
__device__ float g_dt  [2 * BB * LL * DI];       // softplus(dt @ W_dt^T + b)
__device__ float g_y   [2 * BB * LL * DI];       // scan output (pre W_out)

// ---------------- generic tiled SGEMM ----------------
// C[M,N] (+)= A[M,K] @ Bw[N,K]^T
// flipA/flipC: logical row m -> physical row b*L + (L-1-t)   (b=m/1024, t=m%1024)
// epi==1: v = softplus(v + bias[n])
template<int BM, int BN, int BK, int TM, int TN>
__global__ void sgemm_kernel(const float* __restrict__ A, int lda,
                             const float* __restrict__ Bw,
                             float* __restrict__ C, int ldc,
                             int M, int N, int K,
                             int flipA, int flipC, int accumC,
                             int epi, const float* __restrict__ bias)
{
    constexpr int THREADS = (BM / TM) * (BN / TN);
    __shared__ float As[BK][BM];
    __shared__ float Bs[BK][BN];

    const int tid = threadIdx.x;
    const int tx  = tid % (BN / TN);
    const int ty  = tid / (BN / TN);
    const int m0  = blockIdx.y * BM;
    const int n0  = blockIdx.x * BN;

    float acc[TM][TN];
#pragma unroll
    for (int i = 0; i < TM; i++)
#pragma unroll
        for (int j = 0; j < TN; j++) acc[i][j] = 0.f;

    for (int k0 = 0; k0 < K; k0 += BK) {
        // A tile
#pragma unroll 4
        for (int i = tid; i < BM * BK; i += THREADS) {
            int mm = i / BK, kk = i % BK;
            int m  = m0 + mm;
            int row = m;
            if (flipA) { int b = m >> 10, t = m & 1023; row = (b << 10) + (1023 - t); }
            As[kk][mm] = A[(size_t)row * lda + k0 + kk];
        }
        // B tile (weights, row-major [N,K])
#pragma unroll 4
        for (int i = tid; i < BN * BK; i += THREADS) {
            int nn = i / BK, kk = i % BK;
            int n  = n0 + nn;
            Bs[kk][nn] = (n < N) ? Bw[(size_t)n * K + k0 + kk] : 0.f;
        }
        __syncthreads();

#pragma unroll
        for (int kk = 0; kk < BK; kk++) {
            float a[TM], b[TN];
#pragma unroll
            for (int i = 0; i < TM; i++) a[i] = As[kk][ty * TM + i];
#pragma unroll
            for (int j = 0; j < TN; j++) b[j] = Bs[kk][tx * TN + j];
#pragma unroll
            for (int i = 0; i < TM; i++)
#pragma unroll
                for (int j = 0; j < TN; j++) acc[i][j] += a[i] * b[j];
        }
        __syncthreads();
    }

#pragma unroll
    for (int i = 0; i < TM; i++) {
        int m = m0 + ty * TM + i;
        int row = m;
        if (flipC) { int b = m >> 10, t = m & 1023; row = (b << 10) + (1023 - t); }
#pragma unroll
        for (int j = 0; j < TN; j++) {
            int n = n0 + tx * TN + j;
            if (n < N) {
                float v = acc[i][j];
                if (epi == 1) {
                    v += bias[n];
                    v = (v > 20.f) ? v : log1pf(expf(v));
                }
                size_t o = (size_t)row * ldc + n;
                if (accumC) C[o] += v; else C[o] = v;
            }
        }
    }
}

// ---------------- conv (depthwise causal, D_CONV=4) + silu ----------------
__global__ void conv_silu_kernel(const float* __restrict__ cw_f, const float* __restrict__ cb_f,
                                 const float* __restrict__ cw_b, const float* __restrict__ cb_b)
{
    const int TOT = 2 * BB * LL * DI;
    int idx = blockIdx.x * blockDim.x + threadIdx.x;
    if (idx >= TOT) return;
    int d = idx % DI;
    int r = idx / DI;
    int t = r % LL; r /= LL;
    int b = r % BB;
    int dir = r / BB;
    const float* w  = dir ? cw_b : cw_f;
    const float* cb = dir ? cb_b : cb_f;
    const float* xp = g_xz + ((size_t)(dir * BB + b)) * LL * 2 * DI;  // first DI cols of each row
    float s = cb[d];
#pragma unroll
    for (int k = 0; k < 4; k++) {
        int tt = t + k - 3;
        if (tt >= 0) s += w[d * 4 + k] * xp[(size_t)tt * 2 * DI + d];
    }
    float sig = 1.f / (1.f + __expf(-s));
    g_xc[idx] = s * sig;
}

// ---------------- selective scan (one thread per dir,b,d) ----------------
__global__ void scan_kernel(const float* __restrict__ Alog_f, const float* __restrict__ D_f,
                            const float* __restrict__ Alog_b, const float* __restrict__ D_b)
{
    int d   = blockIdx.x * blockDim.x + threadIdx.x;   // 0..DI-1
    int b   = blockIdx.y;
    int dir = blockIdx.z;
    const float* Alog = dir ? Alog_b : Alog_f;
    const float* Dp   = dir ? D_b   : D_f;

    size_t base_di = ((size_t)(dir * BB + b)) * LL * DI;
    size_t base_x  = ((size_t)(dir * BB + b)) * LL * NX;
    size_t base_z  = ((size_t)(dir * BB + b)) * LL * 2 * DI + DI;

    float Areg[DS], h[DS];
#pragma unroll
    for (int s = 0; s < DS; s++) {
        Areg[s] = -__expf(Alog[d * DS + s]);
        h[s] = 0.f;
    }
    const float Dv = Dp[d];

    for (int t = 0; t < LL; t++) {
        float dtv = g_dt[base_di + (size_t)t * DI + d];
        float xv  = g_xc[base_di + (size_t)t * DI + d];
        const float* xd = g_xdbl + base_x + (size_t)t * NX;
        float dx = dtv * xv;
        float y = 0.f;
#pragma unroll
        for (int s = 0; s < DS; s++) {
            float dA = __expf(dtv * Areg[s]);
            h[s] = dA * h[s] + dx * xd[DTR + s];
            y += h[s] * xd[DTR + DS + s];
        }
        y += xv * Dv;
        float z = g_xz[base_z + (size_t)t * 2 * DI + d];
        float sig = 1.f / (1.f + __expf(-z));
        g_y[base_di + (size_t)t * DI + d] = y * (z * sig);
    }
}

// ---------------- out init: out = x ----------------
__global__ void init_out_kernel(float* __restrict__ out, const float* __restrict__ x, int n)
{
    int i = blockIdx.x * blockDim.x + threadIdx.x;
    if (i < n) out[i] = x[i];
}

static inline int cdiv(int a, int b) { return (a + b - 1) / b; }

extern "C" void kernel_launch(void* const* d_in, const int* in_sizes, int n_in,
                              void* d_out, int out_size)
{
    const float* x = (const float*)d_in[0];
    // per-direction params: [0]=fwd offset 1, [1]=bwd offset 10
    const float* W_in[2]   = { (const float*)d_in[1],  (const float*)d_in[10] };
    const float* conv_w[2] = { (const float*)d_in[2],  (const float*)d_in[11] };
    const float* conv_b[2] = { (const float*)d_in[3],  (const float*)d_in[12] };
    const float* W_x[2]    = { (const float*)d_in[4],  (const float*)d_in[13] };
    const float* W_dt[2]   = { (const float*)d_in[5],  (const float*)d_in[14] };
    const float* b_dt[2]   = { (const float*)d_in[6],  (const float*)d_in[15] };
    const float* A_log[2]  = { (const float*)d_in[7],  (const float*)d_in[16] };
    const float* Dvec[2]   = { (const float*)d_in[8],  (const float*)d_in[17] };
    const float* W_out[2]  = { (const float*)d_in[9],  (const float*)d_in[18] };
    float* out = (float*)d_out;

    float *p_xz, *p_xc, *p_xdbl, *p_dt, *p_y;
    cudaGetSymbolAddress((void**)&p_xz,   g_xz);
    cudaGetSymbolAddress((void**)&p_xc,   g_xc);
    cudaGetSymbolAddress((void**)&p_xdbl, g_xdbl);
    cudaGetSymbolAddress((void**)&p_dt,   g_dt);
    cudaGetSymbolAddress((void**)&p_y,    g_y);

    const int M = BB * LL;  // 2048

    // out = x
    {
        int n = BB * LL * DIMM;
        init_out_kernel<<<cdiv(n, 256), 256>>>(out, x, n);
    }

    // 1) xz = x(+flip) @ W_in^T    M=2048 N=3072 K=768
    for (int dir = 0; dir < 2; dir++) {
        dim3 grid(cdiv(2 * DI, 128), cdiv(M, 128));
        sgemm_kernel<128, 128, 8, 8, 8><<<grid, 256>>>(
            x, DIMM, W_in[dir],
            p_xz + (size_t)dir * BB * LL * 2 * DI, 2 * DI,
            M, 2 * DI, DIMM,
            /*flipA=*/dir, 0, 0, 0, nullptr);
    }

    // 2) conv + silu -> g_xc  (both dirs)
    {
        int n = 2 * BB * LL * DI;
        conv_silu_kernel<<<cdiv(n, 256), 256>>>(conv_w[0], conv_b[0], conv_w[1], conv_b[1]);
    }

    // 3) x_dbl = xc @ W_x^T    M=2048 N=80 K=1536 (skinny-N config)
    for (int dir = 0; dir < 2; dir++) {
        dim3 grid(cdiv(NX, 32), cdiv(M, 32));
        sgemm_kernel<32, 32, 16, 2, 2><<<grid, 256>>>(
            p_xc + (size_t)dir * BB * LL * DI, DI, W_x[dir],
            p_xdbl + (size_t)dir * BB * LL * NX, NX,
            M, NX, DI,
            0, 0, 0, 0, nullptr);
    }

    // 4) dt = softplus(x_dbl[:, :48] @ W_dt^T + b_dt)   M=2048 N=1536 K=48
    for (int dir = 0; dir < 2; dir++) {
        dim3 grid(cdiv(DI, 128), cdiv(M, 128));
        sgemm_kernel<128, 128, 8, 8, 8><<<grid, 256>>>(
            p_xdbl + (size_t)dir * BB * LL * NX, NX, W_dt[dir],
            p_dt + (size_t)dir * BB * LL * DI, DI,
            M, DI, DTR,
            0, 0, 0, /*epi=*/1, b_dt[dir]);
    }

    // 5) selective scan + silu(z) gating + D skip -> g_y
    {
        dim3 grid(DI / 128, BB, 2);
        scan_kernel<<<grid, 128>>>(A_log[0], Dvec[0], A_log[1], Dvec[1]);
    }

    // 6) out += y @ W_out^T (bwd stores row-flipped)   M=2048 N=768 K=1536
    for (int dir = 0; dir < 2; dir++) {
        dim3 grid(cdiv(DIMM, 128), cdiv(M, 128));
        sgemm_kernel<128, 128, 8, 8, 8><<<grid, 256>>>(
            p_y + (size_t)dir * BB * LL * DI, DI, W_out[dir],
            out, DIMM,
            M, DIMM, DI,
            0, /*flipC=*/dir, /*accumC=*/1, 0, nullptr);
    }

    (void)in_sizes; (void)n_in; (void)out_size;
}

// round 2
// speedup vs baseline: 2.4327x; 2.4327x over previous
#include <cuda_runtime.h>
#include <math.h>

#define BB   2
#define LL   1024
#define DIMM 768
#define DI   1536
#define DS   16
#define DTR  48
#define NX   80   // DTR + 2*DS
#define XS   8    // split-K for x_dbl

// ---------------- device scratch ----------------
__device__ float g_xz   [2 * BB * LL * 2 * DI];
__device__ float g_xc   [2 * BB * LL * DI];
__device__ float g_xdbl [2 * BB * LL * NX];
__device__ float g_xdblp[XS * 2 * BB * LL * NX];
__device__ float g_dt   [2 * BB * LL * DI];
__device__ float g_y    [2 * BB * LL * DI];

__device__ __forceinline__ int fliprow(int m) {
    return (m & ~1023) + (1023 - (m & 1023));
}

// =======================================================================
// Generic pipelined SGEMM:  C[dir][M,N] = A[dir][M,K] @ W[dir][N,K]^T
// FLIPA: dir==1 reads A rows flipped.  EPI==1: softplus(v + bias[n]).
// Requires: M%BM==0, N%BN==0, K%BK==0, lda%4==0, ldc%4==0.
// =======================================================================
template<int BM, int BN, int BK, int TM, int TN, int FLIPA, int EPI>
__global__ void __launch_bounds__((BM/TM)*(BN/TN), 2)
gemm2(const float* __restrict__ A, int lda, size_t aStride,
      const float* __restrict__ W0, const float* __restrict__ W1,
      float* __restrict__ C, int ldc, size_t cStride,
      int M, int N, int K,
      const float* __restrict__ bias0, const float* __restrict__ bias1)
{
    constexpr int THREADS = (BM/TM)*(BN/TN);
    constexpr int AF4 = BM*BK/4/THREADS;   // float4 A-loads per thread
    constexpr int BF4 = BN*BK/4/THREADS;
    __shared__ float As[BK][BM+4];
    __shared__ float Bs[BK][BN+4];

    const int tid = threadIdx.x;
    const int tx  = tid % (BN/TN);
    const int ty  = tid / (BN/TN);
    const int m0  = blockIdx.y * BM;
    const int n0  = blockIdx.x * BN;
    const int dir = blockIdx.z;

    const float* Ab = A + (size_t)dir * aStride;
    const float* W  = dir ? W1 : W0;
    const float* bias = dir ? bias1 : bias0;
    float* Cb = C + (size_t)dir * cStride;

    // per-thread tile-load coordinates (constant over k0)
    int a_mm[AF4], a_kk[AF4]; const float* a_ptr[AF4];
#pragma unroll
    for (int i = 0; i < AF4; i++) {
        int idx = tid + i * THREADS;
        a_mm[i] = idx / (BK/4);
        a_kk[i] = (idx % (BK/4)) * 4;
        int m = m0 + a_mm[i];
        int row = (FLIPA && dir) ? fliprow(m) : m;
        a_ptr[i] = Ab + (size_t)row * lda + a_kk[i];
    }
    int b_nn[BF4], b_kk[BF4]; const float* b_ptr[BF4];
#pragma unroll
    for (int i = 0; i < BF4; i++) {
        int idx = tid + i * THREADS;
        b_nn[i] = idx / (BK/4);
        b_kk[i] = (idx % (BK/4)) * 4;
        b_ptr[i] = W + (size_t)(n0 + b_nn[i]) * K + b_kk[i];
    }

    float acc[TM][TN];
#pragma unroll
    for (int i = 0; i < TM; i++)
#pragma unroll
        for (int j = 0; j < TN; j++) acc[i][j] = 0.f;

    // ---- initial tile ----
#pragma unroll
    for (int i = 0; i < AF4; i++) {
        float4 v = *(const float4*)(a_ptr[i]);
        As[a_kk[i]+0][a_mm[i]] = v.x; As[a_kk[i]+1][a_mm[i]] = v.y;
        As[a_kk[i]+2][a_mm[i]] = v.z; As[a_kk[i]+3][a_mm[i]] = v.w;
    }
#pragma unroll
    for (int i = 0; i < BF4; i++) {
        float4 v = *(const float4*)(b_ptr[i]);
        Bs[b_kk[i]+0][b_nn[i]] = v.x; Bs[b_kk[i]+1][b_nn[i]] = v.y;
        Bs[b_kk[i]+2][b_nn[i]] = v.z; Bs[b_kk[i]+3][b_nn[i]] = v.w;
    }
    __syncthreads();

    const int nIter = K / BK;
    for (int it = 1; it <= nIter; it++) {
        float4 pa[AF4], pb[BF4];
        if (it < nIter) {
#pragma unroll
            for (int i = 0; i < AF4; i++) pa[i] = *(const float4*)(a_ptr[i] + it*BK);
#pragma unroll
            for (int i = 0; i < BF4; i++) pb[i] = *(const float4*)(b_ptr[i] + it*BK);
        }
        // compute current tile
#pragma unroll
        for (int kk = 0; kk < BK; kk++) {
            float a[TM], b[TN];
#pragma unroll
            for (int i = 0; i < TM; i += 4) {
                float4 v = *(const float4*)&As[kk][ty*TM + i];
                a[i] = v.x; a[i+1] = v.y; a[i+2] = v.z; a[i+3] = v.w;
            }
#pragma unroll
            for (int j = 0; j < TN; j += 4) {
                float4 v = *(const float4*)&Bs[kk][tx*TN + j];
                b[j] = v.x; b[j+1] = v.y; b[j+2] = v.z; b[j+3] = v.w;
            }
#pragma unroll
            for (int i = 0; i < TM; i++)
#pragma unroll
                for (int j = 0; j < TN; j++) acc[i][j] += a[i] * b[j];
        }
        if (it < nIter) {
            __syncthreads();
#pragma unroll
            for (int i = 0; i < AF4; i++) {
                As[a_kk[i]+0][a_mm[i]] = pa[i].x; As[a_kk[i]+1][a_mm[i]] = pa[i].y;
                As[a_kk[i]+2][a_mm[i]] = pa[i].z; As[a_kk[i]+3][a_mm[i]] = pa[i].w;
            }
#pragma unroll
            for (int i = 0; i < BF4; i++) {
                Bs[b_kk[i]+0][b_nn[i]] = pb[i].x; Bs[b_kk[i]+1][b_nn[i]] = pb[i].y;
                Bs[b_kk[i]+2][b_nn[i]] = pb[i].z; Bs[b_kk[i]+3][b_nn[i]] = pb[i].w;
            }
            __syncthreads();
        }
    }

    // ---- epilogue ----
#pragma unroll
    for (int i = 0; i < TM; i++) {
        int m = m0 + ty*TM + i;
#pragma unroll
        for (int j = 0; j < TN; j += 4) {
            int n = n0 + tx*TN + j;
            float4 v = make_float4(acc[i][j], acc[i][j+1], acc[i][j+2], acc[i][j+3]);
            if (EPI == 1) {
                v.x += bias[n+0]; v.y += bias[n+1]; v.z += bias[n+2]; v.w += bias[n+3];
                v.x = (v.x > 20.f) ? v.x : log1pf(expf(v.x));
                v.y = (v.y > 20.f) ? v.y : log1pf(expf(v.y));
                v.z = (v.z > 20.f) ? v.z : log1pf(expf(v.z));
                v.w = (v.w > 20.f) ? v.w : log1pf(expf(v.w));
            }
            *(float4*)&Cb[(size_t)m * ldc + n] = v;
        }
    }
}

// =======================================================================
// Fused output GEMM: out[m,n] = x[m,n] + y0[m]@W0[n] + y1[flip(m)]@W1[n]
// =======================================================================
template<int BM, int BN, int BK, int TM, int TN>
__global__ void __launch_bounds__((BM/TM)*(BN/TN), 2)
wout_kernel(const float* __restrict__ Y, size_t yStride,
            const float* __restrict__ W0, const float* __restrict__ W1,
            const float* __restrict__ X, float* __restrict__ C,
            int N, int K)
{
    constexpr int THREADS = (BM/TM)*(BN/TN);
    constexpr int AF4 = BM*BK/4/THREADS;
    constexpr int BF4 = BN*BK/4/THREADS;
    __shared__ float As[BK][BM+4];
    __shared__ float Bs[BK][BN+4];

    const int tid = threadIdx.x;
    const int tx  = tid % (BN/TN);
    const int ty  = tid / (BN/TN);
    const int m0  = blockIdx.y * BM;
    const int n0  = blockIdx.x * BN;

    int a_mm[AF4], a_kk[AF4];
    int b_nn[BF4], b_kk[BF4];
#pragma unroll
    for (int i = 0; i < AF4; i++) {
        int idx = tid + i * THREADS;
        a_mm[i] = idx / (BK/4); a_kk[i] = (idx % (BK/4)) * 4;
    }
#pragma unroll
    for (int i = 0; i < BF4; i++) {
        int idx = tid + i * THREADS;
        b_nn[i] = idx / (BK/4); b_kk[i] = (idx % (BK/4)) * 4;
    }

    float acc[TM][TN];
#pragma unroll
    for (int i = 0; i < TM; i++)
#pragma unroll
        for (int j = 0; j < TN; j++) acc[i][j] = 0.f;

    for (int dir = 0; dir < 2; dir++) {
        const float* Ab = Y + (size_t)dir * yStride;
        const float* W  = dir ? W1 : W0;
        const float* a_ptr[AF4]; const float* b_ptr[BF4];
#pragma unroll
        for (int i = 0; i < AF4; i++) {
            int m = m0 + a_mm[i];
            int row = dir ? fliprow(m) : m;
            a_ptr[i] = Ab + (size_t)row * K + a_kk[i];
        }
#pragma unroll
        for (int i = 0; i < BF4; i++)
            b_ptr[i] = W + (size_t)(n0 + b_nn[i]) * K + b_kk[i];

        __syncthreads();   // protect smem from previous phase
#pragma unroll
        for (int i = 0; i < AF4; i++) {
            float4 v = *(const float4*)(a_ptr[i]);
            As[a_kk[i]+0][a_mm[i]] = v.x; As[a_kk[i]+1][a_mm[i]] = v.y;
            As[a_kk[i]+2][a_mm[i]] = v.z; As[a_kk[i]+3][a_mm[i]] = v.w;
        }
#pragma unroll
        for (int i = 0; i < BF4; i++) {
            float4 v = *(const float4*)(b_ptr[i]);
            Bs[b_kk[i]+0][b_nn[i]] = v.x; Bs[b_kk[i]+1][b_nn[i]] = v.y;
            Bs[b_kk[i]+2][b_nn[i]] = v.z; Bs[b_kk[i]+3][b_nn[i]] = v.w;
        }
        __syncthreads();

        const int nIter = K / BK;
        for (int it = 1; it <= nIter; it++) {
            float4 pa[AF4], pb[BF4];
            if (it < nIter) {
#pragma unroll
                for (int i = 0; i < AF4; i++) pa[i] = *(const float4*)(a_ptr[i] + it*BK);
#pragma unroll
                for (int i = 0; i < BF4; i++) pb[i] = *(const float4*)(b_ptr[i] + it*BK);
            }
#pragma unroll
            for (int kk = 0; kk < BK; kk++) {
                float a[TM], b[TN];
#pragma unroll
                for (int i = 0; i < TM; i += 4) {
                    float4 v = *(const float4*)&As[kk][ty*TM + i];
                    a[i] = v.x; a[i+1] = v.y; a[i+2] = v.z; a[i+3] = v.w;
                }
#pragma unroll
                for (int j = 0; j < TN; j += 4) {
                    float4 v = *(const float4*)&Bs[kk][tx*TN + j];
                    b[j] = v.x; b[j+1] = v.y; b[j+2] = v.z; b[j+3] = v.w;
                }
#pragma unroll
                for (int i = 0; i < TM; i++)
#pragma unroll
                    for (int j = 0; j < TN; j++) acc[i][j] += a[i] * b[j];
            }
            if (it < nIter) {
                __syncthreads();
#pragma unroll
                for (int i = 0; i < AF4; i++) {
                    As[a_kk[i]+0][a_mm[i]] = pa[i].x; As[a_kk[i]+1][a_mm[i]] = pa[i].y;
                    As[a_kk[i]+2][a_mm[i]] = pa[i].z; As[a_kk[i]+3][a_mm[i]] = pa[i].w;
                }
#pragma unroll
                for (int i = 0; i < BF4; i++) {
                    Bs[b_kk[i]+0][b_nn[i]] = pb[i].x; Bs[b_kk[i]+1][b_nn[i]] = pb[i].y;
                    Bs[b_kk[i]+2][b_nn[i]] = pb[i].z; Bs[b_kk[i]+3][b_nn[i]] = pb[i].w;
                }
                __syncthreads();
            }
        }
    }

    // epilogue: residual add + store
#pragma unroll
    for (int i = 0; i < TM; i++) {
        int m = m0 + ty*TM + i;
#pragma unroll
        for (int j = 0; j < TN; j += 4) {
            int n = n0 + tx*TN + j;
            float4 r = *(const float4*)&X[(size_t)m * N + n];
            float4 v = make_float4(acc[i][j] + r.x, acc[i][j+1] + r.y,
                                   acc[i][j+2] + r.z, acc[i][j+3] + r.w);
            *(float4*)&C[(size_t)m * N + n] = v;
        }
    }
}

// =======================================================================
// x_dbl split-K GEMM: partials[split][dir][m][n], K chunk = 1536/XS
// =======================================================================
__global__ void __launch_bounds__(256, 2)
xdbl_kernel(const float* __restrict__ Wx0, const float* __restrict__ Wx1)
{
    constexpr int BM = 128, BK = 16, KC = DI / XS;  // 192
    __shared__ float As[BK][BM+4];
    __shared__ float Bs[BK][NX+4];

    const int tid = threadIdx.x;
    const int tx  = tid % 16;      // 16 * TN(5) = 80
    const int ty  = tid / 16;      // 16 * TM(8) = 128
    const int m0    = blockIdx.x * BM;
    const int split = blockIdx.y;
    const int dir   = blockIdx.z;

    const float* A = g_xc + (size_t)dir * BB*LL*DI;
    const float* W = dir ? Wx1 : Wx0;
    const int kbase = split * KC;

    float acc[8][5];
#pragma unroll
    for (int i = 0; i < 8; i++)
#pragma unroll
        for (int j = 0; j < 5; j++) acc[i][j] = 0.f;

    for (int k0 = kbase; k0 < kbase + KC; k0 += BK) {
#pragma unroll
        for (int i = 0; i < 2; i++) {
            int idx = tid + i * 256;
            int mm = idx / 4, kk = (idx % 4) * 4;
            float4 v = *(const float4*)&A[(size_t)(m0+mm) * DI + k0 + kk];
            As[kk+0][mm] = v.x; As[kk+1][mm] = v.y; As[kk+2][mm] = v.z; As[kk+3][mm] = v.w;
        }
        for (int i = tid; i < NX * BK; i += 256) {
            int nn = i / BK, kk = i % BK;
            Bs[kk][nn] = W[(size_t)nn * DI + k0 + kk];
        }
        __syncthreads();
#pragma unroll
        for (int kk = 0; kk < BK; kk++) {
            float a[8], b[5];
#pragma unroll
            for (int i = 0; i < 8; i += 4) {
                float4 v = *(const float4*)&As[kk][ty*8 + i];
                a[i] = v.x; a[i+1] = v.y; a[i+2] = v.z; a[i+3] = v.w;
            }
#pragma unroll
            for (int j = 0; j < 5; j++) b[j] = Bs[kk][tx*5 + j];
#pragma unroll
            for (int i = 0; i < 8; i++)
#pragma unroll
                for (int j = 0; j < 5; j++) acc[i][j] += a[i] * b[j];
        }
        __syncthreads();
    }

    float* P = g_xdblp + ((size_t)split * 2 * BB * LL + (size_t)dir * BB * LL) * NX;
#pragma unroll
    for (int i = 0; i < 8; i++) {
        int m = m0 + ty*8 + i;
#pragma unroll
        for (int j = 0; j < 5; j++)
            P[(size_t)m * NX + tx*5 + j] = acc[i][j];
    }
}

__global__ void xdbl_reduce_kernel()
{
    const int N4 = 2 * BB * LL * NX / 4;   // 81920
    int i = blockIdx.x * blockDim.x + threadIdx.x;
    if (i >= N4) return;
    const float4* P = (const float4*)g_xdblp;
    float4 s = P[i];
#pragma unroll
    for (int p = 1; p < XS; p++) {
        float4 v = P[(size_t)p * N4 + i];
        s.x += v.x; s.y += v.y; s.z += v.z; s.w += v.w;
    }
    ((float4*)g_xdbl)[i] = s;
}

// =======================================================================
// conv (depthwise causal, D_CONV=4) + silu, float4 over d
// =======================================================================
__global__ void conv_silu_kernel(const float* __restrict__ cw_f, const float* __restrict__ cb_f,
                                 const float* __restrict__ cw_b, const float* __restrict__ cb_b)
{
    const int TOT4 = 2 * BB * LL * DI / 4;
    int idx = blockIdx.x * blockDim.x + threadIdx.x;
    if (idx >= TOT4) return;
    const int DQ = DI / 4;
    int dq = idx % DQ;
    int r = idx / DQ;
    int t = r % LL; r /= LL;
    int b = r % BB;
    int dir = r / BB;
    int d4 = dq * 4;
    const float* w  = dir ? cw_b : cw_f;
    const float* cb = dir ? cb_b : cb_f;
    const float* xp = g_xz + ((size_t)(dir * BB + b)) * LL * 2 * DI;

    float4 wr0 = *(const float4*)&w[(d4+0)*4];
    float4 wr1 = *(const float4*)&w[(d4+1)*4];
    float4 wr2 = *(const float4*)&w[(d4+2)*4];
    float4 wr3 = *(const float4*)&w[(d4+3)*4];
    float4 s = *(const float4*)&cb[d4];
#pragma unroll
    for (int k = 0; k < 4; k++) {
        int tt = t + k - 3;
        if (tt >= 0) {
            float4 xv = *(const float4*)&xp[(size_t)tt * 2 * DI + d4];
            float w0 = ((const float*)&wr0)[k];
            float w1 = ((const float*)&wr1)[k];
            float w2 = ((const float*)&wr2)[k];
            float w3 = ((const float*)&wr3)[k];
            s.x += w0 * xv.x; s.y += w1 * xv.y; s.z += w2 * xv.z; s.w += w3 * xv.w;
        }
    }
    s.x = s.x / (1.f + __expf(-s.x));
    s.y = s.y / (1.f + __expf(-s.y));
    s.z = s.z / (1.f + __expf(-s.z));
    s.w = s.w / (1.f + __expf(-s.w));
    ((float4*)g_xc)[idx] = s;
}

// =======================================================================
// selective scan: thread = (dir, b, d, s-pair); 8 lanes (s4) per d
// =======================================================================
__global__ void __launch_bounds__(256)
scan_kernel(const float* __restrict__ Alog_f, const float* __restrict__ D_f,
            const float* __restrict__ Alog_b, const float* __restrict__ D_b)
{
    const int tid = threadIdx.x;
    const int s4 = tid & 7;        // handles states 2*s4, 2*s4+1
    const int dl = tid >> 3;       // 0..31
    const int d   = blockIdx.x * 32 + dl;
    const int b   = blockIdx.y;
    const int dir = blockIdx.z;

    const float* Alog = dir ? Alog_b : Alog_f;
    const float* Dp   = dir ? D_b   : D_f;

    const size_t base_di = ((size_t)(dir * BB + b)) * LL * DI;
    const size_t base_x  = ((size_t)(dir * BB + b)) * LL * NX;
    const size_t base_z  = ((size_t)(dir * BB + b)) * LL * 2 * DI + DI;

    float2 Av = *(const float2*)&Alog[d * DS + 2*s4];
    const float A0 = -__expf(Av.x);
    const float A1 = -__expf(Av.y);
    const float Dv = Dp[d];

    const float* pd  = g_dt + base_di + d;
    const float* pxc = g_xc + base_di + d;
    const float* pz  = g_xz + base_z  + d;
    const float* pB  = g_xdbl + base_x + DTR       + 2*s4;
    const float* pC  = g_xdbl + base_x + DTR + DS  + 2*s4;
    float*       py  = g_y  + base_di + d;

    float h0 = 0.f, h1 = 0.f;

    float  dt_c = *pd;
    float  xc_c = *pxc;
    float  z_c  = *pz;
    float2 B_c  = *(const float2*)pB;
    float2 C_c  = *(const float2*)pC;

    for (int t = 0; t < LL; t++) {
        float dt_n = 0.f, xc_n = 0.f, z_n = 0.f;
        float2 B_n = make_float2(0.f, 0.f), C_n = B_n;
        if (t < LL - 1) {
            dt_n = pd[(t+1) * DI];
            xc_n = pxc[(t+1) * DI];
            z_n  = pz[(size_t)(t+1) * 2 * DI];
            B_n  = *(const float2*)(pB + (t+1) * NX);
            C_n  = *(const float2*)(pC + (t+1) * NX);
        }

        float dx  = dt_c * xc_c;
        float dA0 = __expf(dt_c * A0);
        float dA1 = __expf(dt_c * A1);
        h0 = dA0 * h0 + dx * B_c.x;
        h1 = dA1 * h1 + dx * B_c.y;
        float p = h0 * C_c.x + h1 * C_c.y;
        p += __shfl_xor_sync(0xffffffffu, p, 4);
        p += __shfl_xor_sync(0xffffffffu, p, 2);
        p += __shfl_xor_sync(0xffffffffu, p, 1);
        if (s4 == 0) {
            float y = p + xc_c * Dv;
            float sig = 1.f / (1.f + __expf(-z_c));
            py[t * DI] = y * (z_c * sig);
        }

        dt_c = dt_n; xc_c = xc_n; z_c = z_n; B_c = B_n; C_c = C_n;
    }
}

static inline int cdiv(int a, int b) { return (a + b - 1) / b; }

extern "C" void kernel_launch(void* const* d_in, const int* in_sizes, int n_in,
                              void* d_out, int out_size)
{
    const float* x = (const float*)d_in[0];
    const float* W_in[2]   = { (const float*)d_in[1],  (const float*)d_in[10] };
    const float* conv_w[2] = { (const float*)d_in[2],  (const float*)d_in[11] };
    const float* conv_b[2] = { (const float*)d_in[3],  (const float*)d_in[12] };
    const float* W_x[2]    = { (const float*)d_in[4],  (const float*)d_in[13] };
    const float* W_dt[2]   = { (const float*)d_in[5],  (const float*)d_in[14] };
    const float* b_dt[2]   = { (const float*)d_in[6],  (const float*)d_in[15] };
    const float* A_log[2]  = { (const float*)d_in[7],  (const float*)d_in[16] };
    const float* Dvec[2]   = { (const float*)d_in[8],  (const float*)d_in[17] };
    const float* W_out[2]  = { (const float*)d_in[9],  (const float*)d_in[18] };
    float* out = (float*)d_out;

    float *p_xz, *p_xdbl, *p_dt, *p_y;
    cudaGetSymbolAddress((void**)&p_xz,   g_xz);
    cudaGetSymbolAddress((void**)&p_xdbl, g_xdbl);
    cudaGetSymbolAddress((void**)&p_dt,   g_dt);
    cudaGetSymbolAddress((void**)&p_y,    g_y);

    const int M = BB * LL;  // 2048

    // 1) xz = x(+flip) @ W_in^T    M=2048 N=3072 K=768  (both dirs in z)
    {
        dim3 grid(2 * DI / 128, M / 128, 2);
        gemm2<128,128,16,8,8, 1, 0><<<grid, 256>>>(
            x, DIMM, 0,
            W_in[0], W_in[1],
            p_xz, 2 * DI, (size_t)M * 2 * DI,
            M, 2 * DI, DIMM, nullptr, nullptr);
    }

    // 2) conv + silu -> g_xc
    {
        int n4 = 2 * BB * LL * DI / 4;
        conv_silu_kernel<<<cdiv(n4, 256), 256>>>(conv_w[0], conv_b[0], conv_w[1], conv_b[1]);
    }

    // 3) x_dbl = xc @ W_x^T (split-K partials + reduce)
    {
        dim3 grid(M / 128, XS, 2);
        xdbl_kernel<<<grid, 256>>>(W_x[0], W_x[1]);
        int n4 = 2 * BB * LL * NX / 4;
        xdbl_reduce_kernel<<<cdiv(n4, 256), 256>>>();
    }

    // 4) dt = softplus(x_dbl[:, :48] @ W_dt^T + b_dt)   M=2048 N=1536 K=48
    {
        dim3 grid(DI / 128, M / 128, 2);
        gemm2<128,128,16,8,8, 0, 1><<<grid, 256>>>(
            p_xdbl, NX, (size_t)M * NX,
            W_dt[0], W_dt[1],
            p_dt, DI, (size_t)M * DI,
            M, DI, DTR, b_dt[0], b_dt[1]);
    }

    // 5) selective scan + gating -> g_y
    {
        dim3 grid(DI / 32, BB, 2);
        scan_kernel<<<grid, 256>>>(A_log[0], Dvec[0], A_log[1], Dvec[1]);
    }

    // 6) out = x + y0 @ W0^T + flip(y1) @ W1^T   (fused, both dirs)
    {
        dim3 grid(DIMM / 64, M / 128);
        wout_kernel<128,64,16,8,4><<<grid, 256>>>(
            p_y, (size_t)M * DI,
            W_out[0], W_out[1],
            x, out, DIMM, DI);
    }

    (void)in_sizes; (void)n_in; (void)out_size;
}

// round 5
// speedup vs baseline: 3.0680x; 1.2612x over previous
#include <cuda_runtime.h>
#include <cuda_bf16.h>
#include <math.h>
#include <stdint.h>

#define BB   2
#define LL   1024
#define DIMM 768
#define DI   1536
#define DS   16
#define DTR  48
#define NX   80   // DTR + 2*DS
#define XS   8    // split-K for x_dbl

typedef __nv_bfloat16 bf16;

// ---------------- device scratch ----------------
__device__ float g_xz   [2 * BB * LL * 2 * DI];   // [dir][m][3072]
__device__ float g_xc   [2 * BB * LL * DI];
__device__ float g_xdbl [2 * BB * LL * NX];
__device__ float g_xdblp[XS * 2 * BB * LL * NX];
__device__ float g_dt   [2 * BB * LL * DI];

__device__ bf16 g_x_h  [BB * LL * DIMM];
__device__ bf16 g_x_l  [BB * LL * DIMM];
__device__ bf16 g_win_h[2 * 2 * DI * DIMM];
__device__ bf16 g_win_l[2 * 2 * DI * DIMM];
__device__ bf16 g_wout_h[2 * DIMM * DI];
__device__ bf16 g_wout_l[2 * DIMM * DI];
__device__ bf16 g_y_h  [2 * BB * LL * DI];
__device__ bf16 g_y_l  [2 * BB * LL * DI];

__device__ __forceinline__ int fliprow(int m) {
    return (m & ~1023) + (1023 - (m & 1023));
}

__device__ __forceinline__ uint32_t smem_u32(const void* p) {
    uint32_t a;
    asm("{ .reg .u64 t; cvta.to.shared.u64 t, %1; cvt.u32.u64 %0, t; }" : "=r"(a) : "l"(p));
    return a;
}

__device__ __forceinline__ void ldmx4(uint32_t* r, uint32_t addr) {
    asm volatile("ldmatrix.sync.aligned.m8n8.x4.shared.b16 {%0,%1,%2,%3}, [%4];"
        : "=r"(r[0]), "=r"(r[1]), "=r"(r[2]), "=r"(r[3]) : "r"(addr));
}

__device__ __forceinline__ void mma16816(float* d, const uint32_t* a, const uint32_t* b) {
    asm volatile("mma.sync.aligned.m16n8k16.row.col.f32.bf16.bf16.f32 "
        "{%0,%1,%2,%3}, {%4,%5,%6,%7}, {%8,%9}, {%0,%1,%2,%3};"
        : "+f"(d[0]), "+f"(d[1]), "+f"(d[2]), "+f"(d[3])
        : "r"(a[0]), "r"(a[1]), "r"(a[2]), "r"(a[3]), "r"(b[0]), "r"(b[1]));
}

// =======================================================================
// HMMA bf16 split GEMM.
// MODE 0 (xz):   dir = blockIdx.z; C[dir] = sum_pass A_p(x, flip if dir) @ W_p[dir]^T
// MODE 1 (wout): C = X + sum_dir sum_pass A_p(y[dir], flip if dir) @ W_p[dir]^T
// 3 passes per dir: (Ah,Wh), (Al,Wh), (Ah,Wl).  BN=128 fixed, BK=32, K%32==0.
// =======================================================================
template<int MODE, int BM>
__global__ void __launch_bounds__(256)
mma_gemm(const bf16* __restrict__ Ah, const bf16* __restrict__ Al,
         const bf16* __restrict__ Wh, const bf16* __restrict__ Wl,
         float* __restrict__ C, const float* __restrict__ X,
         int K, int ldc, size_t aDirStride, size_t wDirStride, size_t cDirStride)
{
    constexpr int NWM = BM / 32;          // warps along m
    constexpr int NWN = 8 / NWM;          // warps along n
    constexpr int WNW = 128 / NWN;        // warp n-width
    constexpr int NAT = WNW / 8;          // n-atoms per warp
    constexpr int AV  = BM * 4 / 256;     // A vec16 loads per thread
    constexpr int ARS = 80;               // smem row stride (bytes), conflict-free

    __shared__ __align__(16) unsigned char sA[BM * ARS];
    __shared__ __align__(16) unsigned char sB[128 * ARS];

    const int tid  = threadIdx.x;
    const int wid  = tid >> 5;
    const int lane = tid & 31;
    const int warp_m = wid % NWM;
    const int warp_n = wid / NWM;
    const int m0 = blockIdx.y * BM;
    const int n0 = blockIdx.x * 128;

    const uint32_t sA_u = smem_u32(sA);
    const uint32_t sB_u = smem_u32(sB);

    // ldmatrix base addresses (per warp/lane, k-step offset added later)
    const int quad = lane >> 3, liq = lane & 7;
    const int khB = (quad >> 1) * 16;     // byte offset of k-half (8 elems * 2B)
    uint32_t aAddr[2], bAddr[NAT / 2];
#pragma unroll
    for (int ma = 0; ma < 2; ma++) {
        int r = warp_m * 32 + ma * 16 + (quad & 1) * 8 + liq;
        aAddr[ma] = sA_u + r * ARS + khB;
    }
#pragma unroll
    for (int p = 0; p < NAT / 2; p++) {
        int r = warp_n * WNW + p * 16 + (quad & 1) * 8 + liq;
        bAddr[p] = sB_u + r * ARS + khB;
    }

    // global-load coordinates
    int a_row[AV], a_c16[AV];
#pragma unroll
    for (int i = 0; i < AV; i++) {
        int v = tid + i * 256;
        a_row[i] = v >> 2; a_c16[i] = v & 3;
    }
    int b_row[2], b_c16[2];
#pragma unroll
    for (int i = 0; i < 2; i++) {
        int v = tid + i * 256;
        b_row[i] = v >> 2; b_c16[i] = v & 3;
    }

    float acc[2][NAT][4];
#pragma unroll
    for (int ma = 0; ma < 2; ma++)
#pragma unroll
        for (int na = 0; na < NAT; na++)
#pragma unroll
            for (int j = 0; j < 4; j++) acc[ma][na][j] = 0.f;

    const int chunksPerK = K / 32;
    const int nseg = (MODE == 0) ? 3 : 6;
    const int total = nseg * chunksPerK;

    auto load_regs = [&](int c, uint4* ra, uint4* rb) {
        const int seg = c / chunksPerK;
        const int kc = (c % chunksPerK) * 32;
        const int dir = (MODE == 0) ? blockIdx.z : (seg / 3);
        const int pass = seg % 3;
        const bf16* Asrc = ((pass == 1) ? Al : Ah) + (size_t)dir * aDirStride;
        const bf16* Wsrc = ((pass == 2) ? Wl : Wh) + (size_t)dir * wDirStride;
        const bool flip = (dir == 1);
#pragma unroll
        for (int i = 0; i < AV; i++) {
            int m = m0 + a_row[i];
            int row = flip ? fliprow(m) : m;
            ra[i] = *(const uint4*)(Asrc + (size_t)row * K + kc + a_c16[i] * 8);
        }
#pragma unroll
        for (int i = 0; i < 2; i++)
            rb[i] = *(const uint4*)(Wsrc + (size_t)(n0 + b_row[i]) * K + kc + b_c16[i] * 8);
    };

    uint4 ra[AV], rb[2];
    load_regs(0, ra, rb);

    for (int c = 0; c < total; c++) {
        // store prefetched chunk to smem
#pragma unroll
        for (int i = 0; i < AV; i++)
            *(uint4*)(sA + a_row[i] * ARS + a_c16[i] * 16) = ra[i];
#pragma unroll
        for (int i = 0; i < 2; i++)
            *(uint4*)(sB + b_row[i] * ARS + b_c16[i] * 16) = rb[i];
        __syncthreads();

        if (c + 1 < total) load_regs(c + 1, ra, rb);

        // compute: 2 k-steps of m16n8k16
#pragma unroll
        for (int ks = 0; ks < 2; ks++) {
            const int ko = ks * 32;   // 16 elems * 2B
            uint32_t a[2][4];
            ldmx4(a[0], aAddr[0] + ko);
            ldmx4(a[1], aAddr[1] + ko);
            uint32_t b[NAT][2];
#pragma unroll
            for (int p = 0; p < NAT / 2; p++) {
                uint32_t r[4];
                ldmx4(r, bAddr[p] + ko);
                b[2*p][0] = r[0]; b[2*p][1] = r[2];
                b[2*p+1][0] = r[1]; b[2*p+1][1] = r[3];
            }
#pragma unroll
            for (int ma = 0; ma < 2; ma++)
#pragma unroll
                for (int na = 0; na < NAT; na++)
                    mma16816(acc[ma][na], a[ma], b[na]);
        }
        __syncthreads();
    }

    // epilogue
    float* Cd = C + ((MODE == 0) ? (size_t)blockIdx.z * cDirStride : 0);
#pragma unroll
    for (int ma = 0; ma < 2; ma++) {
#pragma unroll
        for (int na = 0; na < NAT; na++) {
            int row = m0 + warp_m * 32 + ma * 16 + (lane >> 2);
            int col = n0 + warp_n * WNW + na * 8 + 2 * (lane & 3);
            float2 v0 = make_float2(acc[ma][na][0], acc[ma][na][1]);
            float2 v1 = make_float2(acc[ma][na][2], acc[ma][na][3]);
            if (MODE == 1) {
                float2 x0 = *(const float2*)&X[(size_t)row * ldc + col];
                float2 x1 = *(const float2*)&X[(size_t)(row + 8) * ldc + col];
                v0.x += x0.x; v0.y += x0.y; v1.x += x1.x; v1.y += x1.y;
            }
            *(float2*)&Cd[(size_t)row * ldc + col] = v0;
            *(float2*)&Cd[(size_t)(row + 8) * ldc + col] = v1;
        }
    }
}

// ==================== hi/lo split prep ====================
__global__ void split_kernel(const float* __restrict__ src,
                             bf16* __restrict__ hi, bf16* __restrict__ lo, int n4)
{
    int i = blockIdx.x * blockDim.x + threadIdx.x;
    if (i >= n4) return;
    float4 v = ((const float4*)src)[i];
    bf16 h0 = __float2bfloat16(v.x), h1 = __float2bfloat16(v.y);
    bf16 h2 = __float2bfloat16(v.z), h3 = __float2bfloat16(v.w);
    bf16 l0 = __float2bfloat16(v.x - __bfloat162float(h0));
    bf16 l1 = __float2bfloat16(v.y - __bfloat162float(h1));
    bf16 l2 = __float2bfloat16(v.z - __bfloat162float(h2));
    bf16 l3 = __float2bfloat16(v.w - __bfloat162float(h3));
    ((__nv_bfloat162*)hi)[2*i]   = __nv_bfloat162(h0, h1);
    ((__nv_bfloat162*)hi)[2*i+1] = __nv_bfloat162(h2, h3);
    ((__nv_bfloat162*)lo)[2*i]   = __nv_bfloat162(l0, l1);
    ((__nv_bfloat162*)lo)[2*i+1] = __nv_bfloat162(l2, l3);
}

// ==================== SIMT GEMM for dt (K=48) ====================
template<int BM, int BN, int BK, int TM, int TN>
__global__ void __launch_bounds__((BM/TM)*(BN/TN), 2)
gemm_dt(const float* __restrict__ A, int lda, size_t aStride,
        const float* __restrict__ W0, const float* __restrict__ W1,
        float* __restrict__ C, int ldc, size_t cStride,
        int M, int N, int K,
        const float* __restrict__ bias0, const float* __restrict__ bias1)
{
    constexpr int THREADS = (BM/TM)*(BN/TN);
    constexpr int AF4 = BM*BK/4/THREADS;
    constexpr int BF4 = BN*BK/4/THREADS;
    __shared__ float As[BK][BM+4];
    __shared__ float Bs[BK][BN+4];

    const int tid = threadIdx.x;
    const int tx  = tid % (BN/TN);
    const int ty  = tid / (BN/TN);
    const int m0  = blockIdx.y * BM;
    const int n0  = blockIdx.x * BN;
    const int dir = blockIdx.z;

    const float* Ab = A + (size_t)dir * aStride;
    const float* W  = dir ? W1 : W0;
    const float* bias = dir ? bias1 : bias0;
    float* Cb = C + (size_t)dir * cStride;

    int a_mm[AF4], a_kk[AF4]; const float* a_ptr[AF4];
#pragma unroll
    for (int i = 0; i < AF4; i++) {
        int idx = tid + i * THREADS;
        a_mm[i] = idx / (BK/4); a_kk[i] = (idx % (BK/4)) * 4;
        a_ptr[i] = Ab + (size_t)(m0 + a_mm[i]) * lda + a_kk[i];
    }
    int b_nn[BF4], b_kk[BF4]; const float* b_ptr[BF4];
#pragma unroll
    for (int i = 0; i < BF4; i++) {
        int idx = tid + i * THREADS;
        b_nn[i] = idx / (BK/4); b_kk[i] = (idx % (BK/4)) * 4;
        b_ptr[i] = W + (size_t)(n0 + b_nn[i]) * K + b_kk[i];
    }

    float acc[TM][TN];
#pragma unroll
    for (int i = 0; i < TM; i++)
#pragma unroll
        for (int j = 0; j < TN; j++) acc[i][j] = 0.f;

    for (int k0 = 0; k0 < K; k0 += BK) {
#pragma unroll
        for (int i = 0; i < AF4; i++) {
            float4 v = *(const float4*)(a_ptr[i] + k0);
            As[a_kk[i]+0][a_mm[i]] = v.x; As[a_kk[i]+1][a_mm[i]] = v.y;
            As[a_kk[i]+2][a_mm[i]] = v.z; As[a_kk[i]+3][a_mm[i]] = v.w;
        }
#pragma unroll
        for (int i = 0; i < BF4; i++) {
            float4 v = *(const float4*)(b_ptr[i] + k0);
            Bs[b_kk[i]+0][b_nn[i]] = v.x; Bs[b_kk[i]+1][b_nn[i]] = v.y;
            Bs[b_kk[i]+2][b_nn[i]] = v.z; Bs[b_kk[i]+3][b_nn[i]] = v.w;
        }
        __syncthreads();
#pragma unroll
        for (int kk = 0; kk < BK; kk++) {
            float a[TM], b[TN];
#pragma unroll
            for (int i = 0; i < TM; i += 4) {
                float4 v = *(const float4*)&As[kk][ty*TM + i];
                a[i] = v.x; a[i+1] = v.y; a[i+2] = v.z; a[i+3] = v.w;
            }
#pragma unroll
            for (int j = 0; j < TN; j += 4) {
                float4 v = *(const float4*)&Bs[kk][tx*TN + j];
                b[j] = v.x; b[j+1] = v.y; b[j+2] = v.z; b[j+3] = v.w;
            }
#pragma unroll
            for (int i = 0; i < TM; i++)
#pragma unroll
                for (int j = 0; j < TN; j++) acc[i][j] += a[i] * b[j];
        }
        __syncthreads();
    }

#pragma unroll
    for (int i = 0; i < TM; i++) {
        int m = m0 + ty*TM + i;
#pragma unroll
        for (int j = 0; j < TN; j += 4) {
            int n = n0 + tx*TN + j;
            float4 v = make_float4(acc[i][j], acc[i][j+1], acc[i][j+2], acc[i][j+3]);
            v.x += bias[n+0]; v.y += bias[n+1]; v.z += bias[n+2]; v.w += bias[n+3];
            v.x = (v.x > 20.f) ? v.x : log1pf(expf(v.x));
            v.y = (v.y > 20.f) ? v.y : log1pf(expf(v.y));
            v.z = (v.z > 20.f) ? v.z : log1pf(expf(v.z));
            v.w = (v.w > 20.f) ? v.w : log1pf(expf(v.w));
            *(float4*)&Cb[(size_t)m * ldc + n] = v;
        }
    }
}

// ==================== x_dbl split-K ====================
__global__ void __launch_bounds__(256, 2)
xdbl_kernel(const float* __restrict__ Wx0, const float* __restrict__ Wx1)
{
    constexpr int BM = 128, BK = 16, KC = DI / XS;
    __shared__ float As[BK][BM+4];
    __shared__ float Bs[BK][NX+4];

    const int tid = threadIdx.x;
    const int tx  = tid % 16;
    const int ty  = tid / 16;
    const int m0    = blockIdx.x * BM;
    const int split = blockIdx.y;
    const int dir   = blockIdx.z;

    const float* A = g_xc + (size_t)dir * BB*LL*DI;
    const float* W = dir ? Wx1 : Wx0;
    const int kbase = split * KC;

    float acc[8][5];
#pragma unroll
    for (int i = 0; i < 8; i++)
#pragma unroll
        for (int j = 0; j < 5; j++) acc[i][j] = 0.f;

    for (int k0 = kbase; k0 < kbase + KC; k0 += BK) {
#pragma unroll
        for (int i = 0; i < 2; i++) {
            int idx = tid + i * 256;
            int mm = idx / 4, kk = (idx % 4) * 4;
            float4 v = *(const float4*)&A[(size_t)(m0+mm) * DI + k0 + kk];
            As[kk+0][mm] = v.x; As[kk+1][mm] = v.y; As[kk+2][mm] = v.z; As[kk+3][mm] = v.w;
        }
        for (int i = tid; i < NX * BK; i += 256) {
            int nn = i / BK, kk = i % BK;
            Bs[kk][nn] = W[(size_t)nn * DI + k0 + kk];
        }
        __syncthreads();
#pragma unroll
        for (int kk = 0; kk < BK; kk++) {
            float a[8], b[5];
#pragma unroll
            for (int i = 0; i < 8; i += 4) {
                float4 v = *(const float4*)&As[kk][ty*8 + i];
                a[i] = v.x; a[i+1] = v.y; a[i+2] = v.z; a[i+3] = v.w;
            }
#pragma unroll
            for (int j = 0; j < 5; j++) b[j] = Bs[kk][tx*5 + j];
#pragma unroll
            for (int i = 0; i < 8; i++)
#pragma unroll
                for (int j = 0; j < 5; j++) acc[i][j] += a[i] * b[j];
        }
        __syncthreads();
    }

    float* P = g_xdblp + ((size_t)split * 2 * BB * LL + (size_t)dir * BB * LL) * NX;
#pragma unroll
    for (int i = 0; i < 8; i++) {
        int m = m0 + ty*8 + i;
#pragma unroll
        for (int j = 0; j < 5; j++)
            P[(size_t)m * NX + tx*5 + j] = acc[i][j];
    }
}

__global__ void xdbl_reduce_kernel()
{
    const int N4 = 2 * BB * LL * NX / 4;
    int i = blockIdx.x * blockDim.x + threadIdx.x;
    if (i >= N4) return;
    const float4* P = (const float4*)g_xdblp;
    float4 s = P[i];
#pragma unroll
    for (int p = 1; p < XS; p++) {
        float4 v = P[(size_t)p * N4 + i];
        s.x += v.x; s.y += v.y; s.z += v.z; s.w += v.w;
    }
    ((float4*)g_xdbl)[i] = s;
}

// ==================== conv + silu ====================
__global__ void conv_silu_kernel(const float* __restrict__ cw_f, const float* __restrict__ cb_f,
                                 const float* __restrict__ cw_b, const float* __restrict__ cb_b)
{
    const int TOT4 = 2 * BB * LL * DI / 4;
    int idx = blockIdx.x * blockDim.x + threadIdx.x;
    if (idx >= TOT4) return;
    const int DQ = DI / 4;
    int dq = idx % DQ;
    int r = idx / DQ;
    int t = r % LL; r /= LL;
    int b = r % BB;
    int dir = r / BB;
    int d4 = dq * 4;
    const float* w  = dir ? cw_b : cw_f;
    const float* cb = dir ? cb_b : cb_f;
    const float* xp = g_xz + ((size_t)(dir * BB + b)) * LL * 2 * DI;

    float4 wr0 = *(const float4*)&w[(d4+0)*4];
    float4 wr1 = *(const float4*)&w[(d4+1)*4];
    float4 wr2 = *(const float4*)&w[(d4+2)*4];
    float4 wr3 = *(const float4*)&w[(d4+3)*4];
    float4 s = *(const float4*)&cb[d4];
#pragma unroll
    for (int k = 0; k < 4; k++) {
        int tt = t + k - 3;
        if (tt >= 0) {
            float4 xv = *(const float4*)&xp[(size_t)tt * 2 * DI + d4];
            s.x += ((const float*)&wr0)[k] * xv.x;
            s.y += ((const float*)&wr1)[k] * xv.y;
            s.z += ((const float*)&wr2)[k] * xv.z;
            s.w += ((const float*)&wr3)[k] * xv.w;
        }
    }
    s.x = s.x / (1.f + __expf(-s.x));
    s.y = s.y / (1.f + __expf(-s.y));
    s.z = s.z / (1.f + __expf(-s.z));
    s.w = s.w / (1.f + __expf(-s.w));
    ((float4*)g_xc)[idx] = s;
}

// ==================== selective scan (emits y as bf16 hi/lo) ====================
__global__ void __launch_bounds__(256)
scan_kernel(const float* __restrict__ Alog_f, const float* __restrict__ D_f,
            const float* __restrict__ Alog_b, const float* __restrict__ D_b)
{
    const int tid = threadIdx.x;
    const int s4 = tid & 7;
    const int dl = tid >> 3;
    const int d   = blockIdx.x * 32 + dl;
    const int b   = blockIdx.y;
    const int dir = blockIdx.z;

    const float* Alog = dir ? Alog_b : Alog_f;
    const float* Dp   = dir ? D_b   : D_f;

    const size_t base_di = ((size_t)(dir * BB + b)) * LL * DI;
    const size_t base_x  = ((size_t)(dir * BB + b)) * LL * NX;
    const size_t base_z  = ((size_t)(dir * BB + b)) * LL * 2 * DI + DI;

    float2 Av = *(const float2*)&Alog[d * DS + 2*s4];
    const float A0 = -__expf(Av.x);
    const float A1 = -__expf(Av.y);
    const float Dv = Dp[d];

    const float* pd  = g_dt + base_di + d;
    const float* pxc = g_xc + base_di + d;
    const float* pz  = g_xz + base_z  + d;
    const float* pB  = g_xdbl + base_x + DTR       + 2*s4;
    const float* pC  = g_xdbl + base_x + DTR + DS  + 2*s4;
    bf16* pyh = g_y_h + base_di + d;
    bf16* pyl = g_y_l + base_di + d;

    float h0 = 0.f, h1 = 0.f;

    float  dt_c = *pd;
    float  xc_c = *pxc;
    float  z_c  = *pz;
    float2 B_c  = *(const float2*)pB;
    float2 C_c  = *(const float2*)pC;

    for (int t = 0; t < LL; t++) {
        float dt_n = 0.f, xc_n = 0.f, z_n = 0.f;
        float2 B_n = make_float2(0.f, 0.f), C_n = B_n;
        if (t < LL - 1) {
            dt_n = pd[(t+1) * DI];
            xc_n = pxc[(t+1) * DI];
            z_n  = pz[(size_t)(t+1) * 2 * DI];
            B_n  = *(const float2*)(pB + (t+1) * NX);
            C_n  = *(const float2*)(pC + (t+1) * NX);
        }

        float dx  = dt_c * xc_c;
        float dA0 = __expf(dt_c * A0);
        float dA1 = __expf(dt_c * A1);
        h0 = dA0 * h0 + dx * B_c.x;
        h1 = dA1 * h1 + dx * B_c.y;
        float p = h0 * C_c.x + h1 * C_c.y;
        p += __shfl_xor_sync(0xffffffffu, p, 4);
        p += __shfl_xor_sync(0xffffffffu, p, 2);
        p += __shfl_xor_sync(0xffffffffu, p, 1);
        if (s4 == 0) {
            float y = p + xc_c * Dv;
            float sig = 1.f / (1.f + __expf(-z_c));
            y = y * (z_c * sig);
            bf16 h = __float2bfloat16(y);
            pyh[t * DI] = h;
            pyl[t * DI] = __float2bfloat16(y - __bfloat162float(h));
        }

        dt_c = dt_n; xc_c = xc_n; z_c = z_n; B_c = B_n; C_c = C_n;
    }
}

static inline int cdiv(int a, int b) { return (a + b - 1) / b; }

extern "C" void kernel_launch(void* const* d_in, const int* in_sizes, int n_in,
                              void* d_out, int out_size)
{
    const float* x = (const float*)d_in[0];
    const float* W_in[2]   = { (const float*)d_in[1],  (const float*)d_in[10] };
    const float* conv_w[2] = { (const float*)d_in[2],  (const float*)d_in[11] };
    const float* conv_b[2] = { (const float*)d_in[3],  (const float*)d_in[12] };
    const float* W_x[2]    = { (const float*)d_in[4],  (const float*)d_in[13] };
    const float* W_dt[2]   = { (const float*)d_in[5],  (const float*)d_in[14] };
    const float* b_dt[2]   = { (const float*)d_in[6],  (const float*)d_in[15] };
    const float* A_log[2]  = { (const float*)d_in[7],  (const float*)d_in[16] };
    const float* Dvec[2]   = { (const float*)d_in[8],  (const float*)d_in[17] };
    const float* W_out[2]  = { (const float*)d_in[9],  (const float*)d_in[18] };
    float* out = (float*)d_out;

    float *p_xz, *p_xdbl, *p_dt;
    cudaGetSymbolAddress((void**)&p_xz,   g_xz);
    cudaGetSymbolAddress((void**)&p_xdbl, g_xdbl);
    cudaGetSymbolAddress((void**)&p_dt,   g_dt);
    bf16 *p_xh, *p_xl, *p_winh, *p_winl, *p_wouth, *p_woutl, *p_yh, *p_yl;
    cudaGetSymbolAddress((void**)&p_xh,    g_x_h);
    cudaGetSymbolAddress((void**)&p_xl,    g_x_l);
    cudaGetSymbolAddress((void**)&p_winh,  g_win_h);
    cudaGetSymbolAddress((void**)&p_winl,  g_win_l);
    cudaGetSymbolAddress((void**)&p_wouth, g_wout_h);
    cudaGetSymbolAddress((void**)&p_woutl, g_wout_l);
    cudaGetSymbolAddress((void**)&p_yh,    g_y_h);
    cudaGetSymbolAddress((void**)&p_yl,    g_y_l);

    const int M = BB * LL;  // 2048

    // 0) hi/lo splits of x and weights
    {
        int n4;
        n4 = M * DIMM / 4;
        split_kernel<<<cdiv(n4, 256), 256>>>(x, p_xh, p_xl, n4);
        n4 = 2 * DI * DIMM / 4;
        split_kernel<<<cdiv(n4, 256), 256>>>(W_in[0], p_winh, p_winl, n4);
        split_kernel<<<cdiv(n4, 256), 256>>>(W_in[1], p_winh + (size_t)2*DI*DIMM, p_winl + (size_t)2*DI*DIMM, n4);
        n4 = DIMM * DI / 4;
        split_kernel<<<cdiv(n4, 256), 256>>>(W_out[0], p_wouth, p_woutl, n4);
        split_kernel<<<cdiv(n4, 256), 256>>>(W_out[1], p_wouth + (size_t)DIMM*DI, p_woutl + (size_t)DIMM*DI, n4);
    }

    // 1) xz = x(+flip) @ W_in^T  (HMMA split-bf16)  M=2048 N=3072 K=768
    {
        dim3 grid(2 * DI / 128, M / 128, 2);
        mma_gemm<0, 128><<<grid, 256>>>(
            p_xh, p_xl, p_winh, p_winl,
            p_xz, nullptr,
            DIMM, 2 * DI,
            0, (size_t)2*DI*DIMM, (size_t)M * 2 * DI);
    }

    // 2) conv + silu -> g_xc
    {
        int n4 = 2 * BB * LL * DI / 4;
        conv_silu_kernel<<<cdiv(n4, 256), 256>>>(conv_w[0], conv_b[0], conv_w[1], conv_b[1]);
    }

    // 3) x_dbl = xc @ W_x^T (split-K + reduce)
    {
        dim3 grid(M / 128, XS, 2);
        xdbl_kernel<<<grid, 256>>>(W_x[0], W_x[1]);
        int n4 = 2 * BB * LL * NX / 4;
        xdbl_reduce_kernel<<<cdiv(n4, 256), 256>>>();
    }

    // 4) dt = softplus(x_dbl[:, :48] @ W_dt^T + b_dt)
    {
        dim3 grid(DI / 128, M / 128, 2);
        gemm_dt<128,128,16,8,8><<<grid, 256>>>(
            p_xdbl, NX, (size_t)M * NX,
            W_dt[0], W_dt[1],
            p_dt, DI, (size_t)M * DI,
            M, DI, DTR, b_dt[0], b_dt[1]);
    }

    // 5) selective scan + gating -> y hi/lo
    {
        dim3 grid(DI / 32, BB, 2);
        scan_kernel<<<grid, 256>>>(A_log[0], Dvec[0], A_log[1], Dvec[1]);
    }

    // 6) out = x + y0 @ W0^T + flip(y1) @ W1^T  (HMMA split-bf16)
    {
        dim3 grid(DIMM / 128, M / 64, 1);
        mma_gemm<1, 64><<<grid, 256>>>(
            p_yh, p_yl, p_wouth, p_woutl,
            out, x,
            DI, DIMM,
            (size_t)M * DI, (size_t)DIMM * DI, 0);
    }

    (void)in_sizes; (void)n_in; (void)out_size;
}

// round 6
// speedup vs baseline: 4.0444x; 1.3183x over previous
#include <cuda_runtime.h>
#include <cuda_bf16.h>
#include <math.h>
#include <stdint.h>

#define BB   2
#define LL   1024
#define DIMM 768
#define DI   1536
#define DS   16
#define DTR  48
#define NX   80   // DTR + 2*DS
#define XS   8    // split-K for x_dbl
#define TT   64   // scan time tile

typedef __nv_bfloat16 bf16;

// ---------------- device scratch ----------------
__device__ float g_xz   [2 * BB * LL * 2 * DI];   // [dir][m][3072]
__device__ float g_xc   [2 * BB * LL * DI];
__device__ float g_xdbl [2 * BB * LL * NX];
__device__ float g_xdblp[XS * 2 * BB * LL * NX];
__device__ float g_dt   [2 * BB * LL * DI];

__device__ bf16 g_x_h  [BB * LL * DIMM];
__device__ bf16 g_x_l  [BB * LL * DIMM];
__device__ bf16 g_win_h[2 * 2 * DI * DIMM];
__device__ bf16 g_win_l[2 * 2 * DI * DIMM];
__device__ bf16 g_wout_h[2 * DIMM * DI];
__device__ bf16 g_wout_l[2 * DIMM * DI];
__device__ bf16 g_y_h  [2 * BB * LL * DI];
__device__ bf16 g_y_l  [2 * BB * LL * DI];

__device__ __forceinline__ int fliprow(int m) {
    return (m & ~1023) + (1023 - (m & 1023));
}

__device__ __forceinline__ uint32_t smem_u32(const void* p) {
    uint32_t a;
    asm("{ .reg .u64 t; cvta.to.shared.u64 t, %1; cvt.u32.u64 %0, t; }" : "=r"(a) : "l"(p));
    return a;
}

__device__ __forceinline__ void ldmx4(uint32_t* r, uint32_t addr) {
    asm volatile("ldmatrix.sync.aligned.m8n8.x4.shared.b16 {%0,%1,%2,%3}, [%4];"
        : "=r"(r[0]), "=r"(r[1]), "=r"(r[2]), "=r"(r[3]) : "r"(addr));
}

__device__ __forceinline__ void mma16816(float* d, const uint32_t* a, const uint32_t* b) {
    asm volatile("mma.sync.aligned.m16n8k16.row.col.f32.bf16.bf16.f32 "
        "{%0,%1,%2,%3}, {%4,%5,%6,%7}, {%8,%9}, {%0,%1,%2,%3};"
        : "+f"(d[0]), "+f"(d[1]), "+f"(d[2]), "+f"(d[3])
        : "r"(a[0]), "r"(a[1]), "r"(a[2]), "r"(a[3]), "r"(b[0]), "r"(b[1]));
}

__device__ __forceinline__ void cp_async16(uint32_t dst, const void* src) {
    asm volatile("cp.async.cg.shared.global [%0], [%1], 16;" :: "r"(dst), "l"(src));
}
__device__ __forceinline__ void cp_commit() {
    asm volatile("cp.async.commit_group;" ::: "memory");
}
template<int N>
__device__ __forceinline__ void cp_wait() {
    asm volatile("cp.async.wait_group %0;" :: "n"(N) : "memory");
}

// =======================================================================
// HMMA bf16 split GEMM, 3-stage cp.async pipeline, one sync per chunk.
// MODE 0 (xz):   dir = blockIdx.z; C[dir] = sum_pass A_p(x, flip if dir) @ W_p[dir]^T
// MODE 1 (wout): C = X + sum_dir sum_pass A_p(y[dir], flip if dir) @ W_p[dir]^T
// 3 passes per dir: (Ah,Wh), (Al,Wh), (Ah,Wl).  BN=128, BK=32, K%32==0.
// =======================================================================
template<int MODE, int BM>
__global__ void __launch_bounds__(256)
mma_gemm(const bf16* __restrict__ Ah, const bf16* __restrict__ Al,
         const bf16* __restrict__ Wh, const bf16* __restrict__ Wl,
         float* __restrict__ C, const float* __restrict__ X,
         int K, int ldc, size_t aDirStride, size_t wDirStride, size_t cDirStride)
{
    constexpr int NWM = BM / 32;
    constexpr int NWN = 8 / NWM;
    constexpr int WNW = 128 / NWN;
    constexpr int NAT = WNW / 8;
    constexpr int AV  = BM * 4 / 256;     // A vec16 cp ops per thread
    constexpr int ARS = 80;               // smem row stride (bytes)
    constexpr int STAGE = (BM + 128) * ARS;

    extern __shared__ __align__(128) unsigned char smem[];
    const uint32_t smem_u = smem_u32(smem);

    const int tid  = threadIdx.x;
    const int wid  = tid >> 5;
    const int lane = tid & 31;
    const int warp_m = wid % NWM;
    const int warp_n = wid / NWM;
    const int m0 = blockIdx.y * BM;
    const int n0 = blockIdx.x * 128;

    // ldmatrix per-lane row offsets (byte offsets within a stage)
    const int quad = lane >> 3, liq = lane & 7;
    const int khB = (quad >> 1) * 16;
    uint32_t aOff[2], bOff[NAT / 2];
#pragma unroll
    for (int ma = 0; ma < 2; ma++) {
        int r = warp_m * 32 + ma * 16 + (quad & 1) * 8 + liq;
        aOff[ma] = r * ARS + khB;
    }
#pragma unroll
    for (int p = 0; p < NAT / 2; p++) {
        int r = warp_n * WNW + p * 16 + (quad & 1) * 8 + liq;
        bOff[p] = BM * ARS + r * ARS + khB;
    }

    // cp.async coords
    int a_row[AV], a_c16[AV];
#pragma unroll
    for (int i = 0; i < AV; i++) {
        int v = tid + i * 256;
        a_row[i] = v >> 2; a_c16[i] = v & 3;
    }
    int b_row[2], b_c16[2];
#pragma unroll
    for (int i = 0; i < 2; i++) {
        int v = tid + i * 256;
        b_row[i] = v >> 2; b_c16[i] = v & 3;
    }

    float acc[2][NAT][4];
#pragma unroll
    for (int ma = 0; ma < 2; ma++)
#pragma unroll
        for (int na = 0; na < NAT; na++)
#pragma unroll
            for (int j = 0; j < 4; j++) acc[ma][na][j] = 0.f;

    const int chunksPerK = K / 32;
    const int nseg = (MODE == 0) ? 3 : 6;
    const int total = nseg * chunksPerK;

    auto issue_stage = [&](int c, int s) {
        const int seg = c / chunksPerK;
        const int kc = (c % chunksPerK) * 32;
        const int dir = (MODE == 0) ? blockIdx.z : (seg / 3);
        const int pass = seg % 3;
        const bf16* Asrc = ((pass == 1) ? Al : Ah) + (size_t)dir * aDirStride;
        const bf16* Wsrc = ((pass == 2) ? Wl : Wh) + (size_t)dir * wDirStride;
        const bool flip = (dir == 1);
        const uint32_t base = smem_u + s * STAGE;
#pragma unroll
        for (int i = 0; i < AV; i++) {
            int m = m0 + a_row[i];
            int row = flip ? fliprow(m) : m;
            cp_async16(base + a_row[i] * ARS + a_c16[i] * 16,
                       Asrc + (size_t)row * K + kc + a_c16[i] * 8);
        }
#pragma unroll
        for (int i = 0; i < 2; i++) {
            cp_async16(base + BM * ARS + b_row[i] * ARS + b_c16[i] * 16,
                       Wsrc + (size_t)(n0 + b_row[i]) * K + kc + b_c16[i] * 8);
        }
        cp_commit();
    };

    issue_stage(0, 0);
    issue_stage(1, 1);

    for (int c = 0; c < total; c++) {
        if (c + 2 < total) cp_wait<1>(); else cp_wait<0>();
        __syncthreads();
        if (c + 2 < total) issue_stage(c + 2, (c + 2) % 3);

        const uint32_t sbase = smem_u + (c % 3) * STAGE;
#pragma unroll
        for (int ks = 0; ks < 2; ks++) {
            const int ko = ks * 32;
            uint32_t a[2][4];
            ldmx4(a[0], sbase + aOff[0] + ko);
            ldmx4(a[1], sbase + aOff[1] + ko);
            uint32_t b[NAT][2];
#pragma unroll
            for (int p = 0; p < NAT / 2; p++) {
                uint32_t r[4];
                ldmx4(r, sbase + bOff[p] + ko);
                b[2*p][0] = r[0]; b[2*p][1] = r[2];
                b[2*p+1][0] = r[1]; b[2*p+1][1] = r[3];
            }
#pragma unroll
            for (int ma = 0; ma < 2; ma++)
#pragma unroll
                for (int na = 0; na < NAT; na++)
                    mma16816(acc[ma][na], a[ma], b[na]);
        }
    }
    __syncthreads();

    // epilogue
    float* Cd = C + ((MODE == 0) ? (size_t)blockIdx.z * cDirStride : 0);
#pragma unroll
    for (int ma = 0; ma < 2; ma++) {
#pragma unroll
        for (int na = 0; na < NAT; na++) {
            int row = m0 + warp_m * 32 + ma * 16 + (lane >> 2);
            int col = n0 + warp_n * WNW + na * 8 + 2 * (lane & 3);
            float2 v0 = make_float2(acc[ma][na][0], acc[ma][na][1]);
            float2 v1 = make_float2(acc[ma][na][2], acc[ma][na][3]);
            if (MODE == 1) {
                float2 x0 = *(const float2*)&X[(size_t)row * ldc + col];
                float2 x1 = *(const float2*)&X[(size_t)(row + 8) * ldc + col];
                v0.x += x0.x; v0.y += x0.y; v1.x += x1.x; v1.y += x1.y;
            }
            *(float2*)&Cd[(size_t)row * ldc + col] = v0;
            *(float2*)&Cd[(size_t)(row + 8) * ldc + col] = v1;
        }
    }
}

// ==================== hi/lo split prep ====================
__global__ void split_kernel(const float* __restrict__ src,
                             bf16* __restrict__ hi, bf16* __restrict__ lo, int n4)
{
    int i = blockIdx.x * blockDim.x + threadIdx.x;
    if (i >= n4) return;
    float4 v = ((const float4*)src)[i];
    bf16 h0 = __float2bfloat16(v.x), h1 = __float2bfloat16(v.y);
    bf16 h2 = __float2bfloat16(v.z), h3 = __float2bfloat16(v.w);
    bf16 l0 = __float2bfloat16(v.x - __bfloat162float(h0));
    bf16 l1 = __float2bfloat16(v.y - __bfloat162float(h1));
    bf16 l2 = __float2bfloat16(v.z - __bfloat162float(h2));
    bf16 l3 = __float2bfloat16(v.w - __bfloat162float(h3));
    ((__nv_bfloat162*)hi)[2*i]   = __nv_bfloat162(h0, h1);
    ((__nv_bfloat162*)hi)[2*i+1] = __nv_bfloat162(h2, h3);
    ((__nv_bfloat162*)lo)[2*i]   = __nv_bfloat162(l0, l1);
    ((__nv_bfloat162*)lo)[2*i+1] = __nv_bfloat162(l2, l3);
}

// ==================== SIMT GEMM for dt (K=48) ====================
template<int BM, int BN, int BK, int TM, int TN>
__global__ void __launch_bounds__((BM/TM)*(BN/TN), 2)
gemm_dt(const float* __restrict__ A, int lda, size_t aStride,
        const float* __restrict__ W0, const float* __restrict__ W1,
        float* __restrict__ C, int ldc, size_t cStride,
        int M, int N, int K,
        const float* __restrict__ bias0, const float* __restrict__ bias1)
{
    constexpr int THREADS = (BM/TM)*(BN/TN);
    constexpr int AF4 = BM*BK/4/THREADS;
    constexpr int BF4 = BN*BK/4/THREADS;
    __shared__ float As[BK][BM+4];
    __shared__ float Bs[BK][BN+4];

    const int tid = threadIdx.x;
    const int tx  = tid % (BN/TN);
    const int ty  = tid / (BN/TN);
    const int m0  = blockIdx.y * BM;
    const int n0  = blockIdx.x * BN;
    const int dir = blockIdx.z;

    const float* Ab = A + (size_t)dir * aStride;
    const float* W  = dir ? W1 : W0;
    const float* bias = dir ? bias1 : bias0;
    float* Cb = C + (size_t)dir * cStride;

    int a_mm[AF4], a_kk[AF4]; const float* a_ptr[AF4];
#pragma unroll
    for (int i = 0; i < AF4; i++) {
        int idx = tid + i * THREADS;
        a_mm[i] = idx / (BK/4); a_kk[i] = (idx % (BK/4)) * 4;
        a_ptr[i] = Ab + (size_t)(m0 + a_mm[i]) * lda + a_kk[i];
    }
    int b_nn[BF4], b_kk[BF4]; const float* b_ptr[BF4];
#pragma unroll
    for (int i = 0; i < BF4; i++) {
        int idx = tid + i * THREADS;
        b_nn[i] = idx / (BK/4); b_kk[i] = (idx % (BK/4)) * 4;
        b_ptr[i] = W + (size_t)(n0 + b_nn[i]) * K + b_kk[i];
    }

    float acc[TM][TN];
#pragma unroll
    for (int i = 0; i < TM; i++)
#pragma unroll
        for (int j = 0; j < TN; j++) acc[i][j] = 0.f;

    for (int k0 = 0; k0 < K; k0 += BK) {
#pragma unroll
        for (int i = 0; i < AF4; i++) {
            float4 v = *(const float4*)(a_ptr[i] + k0);
            As[a_kk[i]+0][a_mm[i]] = v.x; As[a_kk[i]+1][a_mm[i]] = v.y;
            As[a_kk[i]+2][a_mm[i]] = v.z; As[a_kk[i]+3][a_mm[i]] = v.w;
        }
#pragma unroll
        for (int i = 0; i < BF4; i++) {
            float4 v = *(const float4*)(b_ptr[i] + k0);
            Bs[b_kk[i]+0][b_nn[i]] = v.x; Bs[b_kk[i]+1][b_nn[i]] = v.y;
            Bs[b_kk[i]+2][b_nn[i]] = v.z; Bs[b_kk[i]+3][b_nn[i]] = v.w;
        }
        __syncthreads();
#pragma unroll
        for (int kk = 0; kk < BK; kk++) {
            float a[TM], b[TN];
#pragma unroll
            for (int i = 0; i < TM; i += 4) {
                float4 v = *(const float4*)&As[kk][ty*TM + i];
                a[i] = v.x; a[i+1] = v.y; a[i+2] = v.z; a[i+3] = v.w;
            }
#pragma unroll
            for (int j = 0; j < TN; j += 4) {
                float4 v = *(const float4*)&Bs[kk][tx*TN + j];
                b[j] = v.x; b[j+1] = v.y; b[j+2] = v.z; b[j+3] = v.w;
            }
#pragma unroll
            for (int i = 0; i < TM; i++)
#pragma unroll
                for (int j = 0; j < TN; j++) acc[i][j] += a[i] * b[j];
        }
        __syncthreads();
    }

#pragma unroll
    for (int i = 0; i < TM; i++) {
        int m = m0 + ty*TM + i;
#pragma unroll
        for (int j = 0; j < TN; j += 4) {
            int n = n0 + tx*TN + j;
            float4 v = make_float4(acc[i][j], acc[i][j+1], acc[i][j+2], acc[i][j+3]);
            v.x += bias[n+0]; v.y += bias[n+1]; v.z += bias[n+2]; v.w += bias[n+3];
            v.x = (v.x > 20.f) ? v.x : log1pf(expf(v.x));
            v.y = (v.y > 20.f) ? v.y : log1pf(expf(v.y));
            v.z = (v.z > 20.f) ? v.z : log1pf(expf(v.z));
            v.w = (v.w > 20.f) ? v.w : log1pf(expf(v.w));
            *(float4*)&Cb[(size_t)m * ldc + n] = v;
        }
    }
}

// ==================== x_dbl split-K ====================
__global__ void __launch_bounds__(256, 2)
xdbl_kernel(const float* __restrict__ Wx0, const float* __restrict__ Wx1)
{
    constexpr int BM = 128, BK = 16, KC = DI / XS;
    __shared__ float As[BK][BM+4];
    __shared__ float Bs[BK][NX+4];

    const int tid = threadIdx.x;
    const int tx  = tid % 16;
    const int ty  = tid / 16;
    const int m0    = blockIdx.x * BM;
    const int split = blockIdx.y;
    const int dir   = blockIdx.z;

    const float* A = g_xc + (size_t)dir * BB*LL*DI;
    const float* W = dir ? Wx1 : Wx0;
    const int kbase = split * KC;

    float acc[8][5];
#pragma unroll
    for (int i = 0; i < 8; i++)
#pragma unroll
        for (int j = 0; j < 5; j++) acc[i][j] = 0.f;

    for (int k0 = kbase; k0 < kbase + KC; k0 += BK) {
#pragma unroll
        for (int i = 0; i < 2; i++) {
            int idx = tid + i * 256;
            int mm = idx / 4, kk = (idx % 4) * 4;
            float4 v = *(const float4*)&A[(size_t)(m0+mm) * DI + k0 + kk];
            As[kk+0][mm] = v.x; As[kk+1][mm] = v.y; As[kk+2][mm] = v.z; As[kk+3][mm] = v.w;
        }
        for (int i = tid; i < NX * BK; i += 256) {
            int nn = i / BK, kk = i % BK;
            Bs[kk][nn] = W[(size_t)nn * DI + k0 + kk];
        }
        __syncthreads();
#pragma unroll
        for (int kk = 0; kk < BK; kk++) {
            float a[8], b[5];
#pragma unroll
            for (int i = 0; i < 8; i += 4) {
                float4 v = *(const float4*)&As[kk][ty*8 + i];
                a[i] = v.x; a[i+1] = v.y; a[i+2] = v.z; a[i+3] = v.w;
            }
#pragma unroll
            for (int j = 0; j < 5; j++) b[j] = Bs[kk][tx*5 + j];
#pragma unroll
            for (int i = 0; i < 8; i++)
#pragma unroll
                for (int j = 0; j < 5; j++) acc[i][j] += a[i] * b[j];
        }
        __syncthreads();
    }

    float* P = g_xdblp + ((size_t)split * 2 * BB * LL + (size_t)dir * BB * LL) * NX;
#pragma unroll
    for (int i = 0; i < 8; i++) {
        int m = m0 + ty*8 + i;
#pragma unroll
        for (int j = 0; j < 5; j++)
            P[(size_t)m * NX + tx*5 + j] = acc[i][j];
    }
}

__global__ void xdbl_reduce_kernel()
{
    const int N4 = 2 * BB * LL * NX / 4;
    int i = blockIdx.x * blockDim.x + threadIdx.x;
    if (i >= N4) return;
    const float4* P = (const float4*)g_xdblp;
    float4 s = P[i];
#pragma unroll
    for (int p = 1; p < XS; p++) {
        float4 v = P[(size_t)p * N4 + i];
        s.x += v.x; s.y += v.y; s.z += v.z; s.w += v.w;
    }
    ((float4*)g_xdbl)[i] = s;
}

// ==================== conv + silu ====================
__global__ void conv_silu_kernel(const float* __restrict__ cw_f, const float* __restrict__ cb_f,
                                 const float* __restrict__ cw_b, const float* __restrict__ cb_b)
{
    const int TOT4 = 2 * BB * LL * DI / 4;
    int idx = blockIdx.x * blockDim.x + threadIdx.x;
    if (idx >= TOT4) return;
    const int DQ = DI / 4;
    int dq = idx % DQ;
    int r = idx / DQ;
    int t = r % LL; r /= LL;
    int b = r % BB;
    int dir = r / BB;
    int d4 = dq * 4;
    const float* w  = dir ? cw_b : cw_f;
    const float* cb = dir ? cb_b : cb_f;
    const float* xp = g_xz + ((size_t)(dir * BB + b)) * LL * 2 * DI;

    float4 wr0 = *(const float4*)&w[(d4+0)*4];
    float4 wr1 = *(const float4*)&w[(d4+1)*4];
    float4 wr2 = *(const float4*)&w[(d4+2)*4];
    float4 wr3 = *(const float4*)&w[(d4+3)*4];
    float4 s = *(const float4*)&cb[d4];
#pragma unroll
    for (int k = 0; k < 4; k++) {
        int tt = t + k - 3;
        if (tt >= 0) {
            float4 xv = *(const float4*)&xp[(size_t)tt * 2 * DI + d4];
            s.x += ((const float*)&wr0)[k] * xv.x;
            s.y += ((const float*)&wr1)[k] * xv.y;
            s.z += ((const float*)&wr2)[k] * xv.z;
            s.w += ((const float*)&wr3)[k] * xv.w;
        }
    }
    s.x = s.x / (1.f + __expf(-s.x));
    s.y = s.y / (1.f + __expf(-s.y));
    s.z = s.z / (1.f + __expf(-s.z));
    s.w = s.w / (1.f + __expf(-s.w));
    ((float4*)g_xc)[idx] = s;
}

// ==================== selective scan v2 (smem time-tiled) ====================
__global__ void __launch_bounds__(256)
scan_kernel(const float* __restrict__ Alog_f, const float* __restrict__ D_f,
            const float* __restrict__ Alog_b, const float* __restrict__ D_b)
{
    __shared__ float s_dt[TT][32], s_xc[TT][32], s_z[TT][32], s_bc[TT][32];
    __shared__ bf16  s_yh[TT][32], s_yl[TT][32];

    const int tid = threadIdx.x;
    const int s4 = tid & 7;
    const int dl = tid >> 3;
    const int d0  = blockIdx.x * 32;
    const int b   = blockIdx.y;
    const int dir = blockIdx.z;

    const float* Alog = dir ? Alog_b : Alog_f;
    const float* Dp   = dir ? D_b   : D_f;

    const size_t base_di = ((size_t)(dir * BB + b)) * LL * DI;
    const size_t base_x  = ((size_t)(dir * BB + b)) * LL * NX;
    const size_t base_z  = ((size_t)(dir * BB + b)) * LL * 2 * DI + DI;

    float2 Av = *(const float2*)&Alog[(d0 + dl) * DS + 2*s4];
    const float A0 = -__expf(Av.x);
    const float A1 = -__expf(Av.y);
    const float Dv = Dp[d0 + dl];

    float h0 = 0.f, h1 = 0.f;

    for (int t0 = 0; t0 < LL; t0 += TT) {
        // cooperative coalesced load of the tile
#pragma unroll
        for (int i = tid; i < TT * 32; i += 256) {
            int t = i >> 5, d = i & 31;
            size_t r = base_di + (size_t)(t0 + t) * DI + d0 + d;
            s_dt[t][d] = g_dt[r];
            s_xc[t][d] = g_xc[r];
            s_z [t][d] = g_xz[base_z + (size_t)(t0 + t) * 2 * DI + d0 + d];
            s_bc[t][d] = g_xdbl[base_x + (size_t)(t0 + t) * NX + DTR + d];
        }
        __syncthreads();

#pragma unroll 8
        for (int t = 0; t < TT; t++) {
            float dtv = s_dt[t][dl];
            float xcv = s_xc[t][dl];
            float B0 = s_bc[t][2*s4],      B1 = s_bc[t][2*s4 + 1];
            float C0 = s_bc[t][16 + 2*s4], C1 = s_bc[t][17 + 2*s4];
            float dx  = dtv * xcv;
            h0 = __expf(dtv * A0) * h0 + dx * B0;
            h1 = __expf(dtv * A1) * h1 + dx * B1;
            float p = h0 * C0 + h1 * C1;
            p += __shfl_xor_sync(0xffffffffu, p, 4);
            p += __shfl_xor_sync(0xffffffffu, p, 2);
            p += __shfl_xor_sync(0xffffffffu, p, 1);
            if (s4 == 0) {
                float zv = s_z[t][dl];
                float y = p + xcv * Dv;
                float sig = 1.f / (1.f + __expf(-zv));
                y = y * (zv * sig);
                bf16 h = __float2bfloat16(y);
                s_yh[t][dl] = h;
                s_yl[t][dl] = __float2bfloat16(y - __bfloat162float(h));
            }
        }
        __syncthreads();

        // coalesced store of y tile
#pragma unroll
        for (int i = tid; i < TT * 32; i += 256) {
            int t = i >> 5, d = i & 31;
            size_t r = base_di + (size_t)(t0 + t) * DI + d0 + d;
            g_y_h[r] = s_yh[t][d];
            g_y_l[r] = s_yl[t][d];
        }
        __syncthreads();
    }
}

static inline int cdiv(int a, int b) { return (a + b - 1) / b; }

extern "C" void kernel_launch(void* const* d_in, const int* in_sizes, int n_in,
                              void* d_out, int out_size)
{
    const float* x = (const float*)d_in[0];
    const float* W_in[2]   = { (const float*)d_in[1],  (const float*)d_in[10] };
    const float* conv_w[2] = { (const float*)d_in[2],  (const float*)d_in[11] };
    const float* conv_b[2] = { (const float*)d_in[3],  (const float*)d_in[12] };
    const float* W_x[2]    = { (const float*)d_in[4],  (const float*)d_in[13] };
    const float* W_dt[2]   = { (const float*)d_in[5],  (const float*)d_in[14] };
    const float* b_dt[2]   = { (const float*)d_in[6],  (const float*)d_in[15] };
    const float* A_log[2]  = { (const float*)d_in[7],  (const float*)d_in[16] };
    const float* Dvec[2]   = { (const float*)d_in[8],  (const float*)d_in[17] };
    const float* W_out[2]  = { (const float*)d_in[9],  (const float*)d_in[18] };
    float* out = (float*)d_out;

    float *p_xz, *p_xdbl, *p_dt;
    cudaGetSymbolAddress((void**)&p_xz,   g_xz);
    cudaGetSymbolAddress((void**)&p_xdbl, g_xdbl);
    cudaGetSymbolAddress((void**)&p_dt,   g_dt);
    bf16 *p_xh, *p_xl, *p_winh, *p_winl, *p_wouth, *p_woutl, *p_yh, *p_yl;
    cudaGetSymbolAddress((void**)&p_xh,    g_x_h);
    cudaGetSymbolAddress((void**)&p_xl,    g_x_l);
    cudaGetSymbolAddress((void**)&p_winh,  g_win_h);
    cudaGetSymbolAddress((void**)&p_winl,  g_win_l);
    cudaGetSymbolAddress((void**)&p_wouth, g_wout_h);
    cudaGetSymbolAddress((void**)&p_woutl, g_wout_l);
    cudaGetSymbolAddress((void**)&p_yh,    g_y_h);
    cudaGetSymbolAddress((void**)&p_yl,    g_y_l);

    const int M = BB * LL;  // 2048

    const int SMEM_G0 = 3 * (128 + 128) * 80;   // 61440
    const int SMEM_G1 = 3 * (64 + 128) * 80;    // 46080
    cudaFuncSetAttribute(mma_gemm<0,128>, cudaFuncAttributeMaxDynamicSharedMemorySize, SMEM_G0);
    cudaFuncSetAttribute(mma_gemm<1,64>,  cudaFuncAttributeMaxDynamicSharedMemorySize, SMEM_G1);

    // 0) hi/lo splits of x and weights
    {
        int n4;
        n4 = M * DIMM / 4;
        split_kernel<<<cdiv(n4, 256), 256>>>(x, p_xh, p_xl, n4);
        n4 = 2 * DI * DIMM / 4;
        split_kernel<<<cdiv(n4, 256), 256>>>(W_in[0], p_winh, p_winl, n4);
        split_kernel<<<cdiv(n4, 256), 256>>>(W_in[1], p_winh + (size_t)2*DI*DIMM, p_winl + (size_t)2*DI*DIMM, n4);
        n4 = DIMM * DI / 4;
        split_kernel<<<cdiv(n4, 256), 256>>>(W_out[0], p_wouth, p_woutl, n4);
        split_kernel<<<cdiv(n4, 256), 256>>>(W_out[1], p_wouth + (size_t)DIMM*DI, p_woutl + (size_t)DIMM*DI, n4);
    }

    // 1) xz = x(+flip) @ W_in^T  (HMMA split-bf16, cp.async pipeline)
    {
        dim3 grid(2 * DI / 128, M / 128, 2);
        mma_gemm<0, 128><<<grid, 256, SMEM_G0>>>(
            p_xh, p_xl, p_winh, p_winl,
            p_xz, nullptr,
            DIMM, 2 * DI,
            0, (size_t)2*DI*DIMM, (size_t)M * 2 * DI);
    }

    // 2) conv + silu -> g_xc
    {
        int n4 = 2 * BB * LL * DI / 4;
        conv_silu_kernel<<<cdiv(n4, 256), 256>>>(conv_w[0], conv_b[0], conv_w[1], conv_b[1]);
    }

    // 3) x_dbl = xc @ W_x^T (split-K + reduce)
    {
        dim3 grid(M / 128, XS, 2);
        xdbl_kernel<<<grid, 256>>>(W_x[0], W_x[1]);
        int n4 = 2 * BB * LL * NX / 4;
        xdbl_reduce_kernel<<<cdiv(n4, 256), 256>>>();
    }

    // 4) dt = softplus(x_dbl[:, :48] @ W_dt^T + b_dt)
    {
        dim3 grid(DI / 128, M / 128, 2);
        gemm_dt<128,128,16,8,8><<<grid, 256>>>(
            p_xdbl, NX, (size_t)M * NX,
            W_dt[0], W_dt[1],
            p_dt, DI, (size_t)M * DI,
            M, DI, DTR, b_dt[0], b_dt[1]);
    }

    // 5) selective scan + gating -> y hi/lo  (smem time-tiled)
    {
        dim3 grid(DI / 32, BB, 2);
        scan_kernel<<<grid, 256>>>(A_log[0], Dvec[0], A_log[1], Dvec[1]);
    }

    // 6) out = x + y0 @ W0^T + flip(y1) @ W1^T  (HMMA split-bf16)
    {
        dim3 grid(DIMM / 128, M / 64, 1);
        mma_gemm<1, 64><<<grid, 256, SMEM_G1>>>(
            p_yh, p_yl, p_wouth, p_woutl,
            out, x,
            DI, DIMM,
            (size_t)M * DI, (size_t)DIMM * DI, 0);
    }

    (void)in_sizes; (void)n_in; (void)out_size;
}

// round 8
// speedup vs baseline: 4.3311x; 1.0709x over previous
#include <cuda_runtime.h>
#include <cuda_bf16.h>
#include <math.h>
#include <stdint.h>

#define BB   2
#define LL   1024
#define DIMM 768
#define DI   1536
#define DS   16
#define DTR  48
#define NX   80   // DTR + 2*DS
#define XS   8    // split-K for x_dbl
#define TT   64   // scan time tile

typedef __nv_bfloat16 bf16;

// ---------------- device scratch ----------------
__device__ float g_xz   [2 * BB * LL * 2 * DI];   // [dir][m][3072]
__device__ float g_xc   [2 * BB * LL * DI];
__device__ float g_xdbl [2 * BB * LL * NX];
__device__ float g_xdblp[XS * 2 * BB * LL * NX];
__device__ float g_dt   [2 * BB * LL * DI];

__device__ bf16 g_x_h  [BB * LL * DIMM];
__device__ bf16 g_x_l  [BB * LL * DIMM];
__device__ bf16 g_win_h[2 * 2 * DI * DIMM];
__device__ bf16 g_win_l[2 * 2 * DI * DIMM];
__device__ bf16 g_wout_h[2 * DIMM * DI];
__device__ bf16 g_wout_l[2 * DIMM * DI];
__device__ bf16 g_y_h  [2 * BB * LL * DI];
__device__ bf16 g_y_l  [2 * BB * LL * DI];

__device__ __forceinline__ int fliprow(int m) {
    return (m & ~1023) + (1023 - (m & 1023));
}

__device__ __forceinline__ uint32_t smem_u32(const void* p) {
    uint32_t a;
    asm("{ .reg .u64 t; cvta.to.shared.u64 t, %1; cvt.u32.u64 %0, t; }" : "=r"(a) : "l"(p));
    return a;
}

__device__ __forceinline__ void ldmx4(uint32_t* r, uint32_t addr) {
    asm volatile("ldmatrix.sync.aligned.m8n8.x4.shared.b16 {%0,%1,%2,%3}, [%4];"
        : "=r"(r[0]), "=r"(r[1]), "=r"(r[2]), "=r"(r[3]) : "r"(addr));
}

__device__ __forceinline__ void mma16816(float* d, const uint32_t* a, const uint32_t* b) {
    asm volatile("mma.sync.aligned.m16n8k16.row.col.f32.bf16.bf16.f32 "
        "{%0,%1,%2,%3}, {%4,%5,%6,%7}, {%8,%9}, {%0,%1,%2,%3};"
        : "+f"(d[0]), "+f"(d[1]), "+f"(d[2]), "+f"(d[3])
        : "r"(a[0]), "r"(a[1]), "r"(a[2]), "r"(a[3]), "r"(b[0]), "r"(b[1]));
}

__device__ __forceinline__ void cp_async16(uint32_t dst, const void* src) {
    asm volatile("cp.async.cg.shared.global [%0], [%1], 16;" :: "r"(dst), "l"(src));
}
__device__ __forceinline__ void cp_commit() {
    asm volatile("cp.async.commit_group;" ::: "memory");
}
template<int N>
__device__ __forceinline__ void cp_wait() {
    asm volatile("cp.async.wait_group %0;" :: "n"(N) : "memory");
}

// =======================================================================
// HMMA bf16 split GEMM v3: fused 3-product K-chunks.
// Per chunk load Ah,Al,Wh,Wl once; compute Ah*Wh + Al*Wh + Ah*Wl.
// MODE 0 (xz):   dir = blockIdx.z; C[dir] = A(x, flip if dir) @ W[dir]^T
// MODE 1 (wout): C = X + sum_dir A(y[dir], flip if dir) @ W[dir]^T
// BN=128, BK=32, K%32==0. 2-stage cp.async ring.
// =======================================================================
template<int MODE, int BM>
__global__ void __launch_bounds__(256)
mma_gemm(const bf16* __restrict__ Ah, const bf16* __restrict__ Al,
         const bf16* __restrict__ Wh, const bf16* __restrict__ Wl,
         float* __restrict__ C, const float* __restrict__ X,
         int K, int ldc, size_t aDirStride, size_t wDirStride, size_t cDirStride)
{
    constexpr int NWM = BM / 32;
    constexpr int NWN = 8 / NWM;
    constexpr int WNW = 128 / NWN;
    constexpr int NAT = WNW / 8;
    constexpr int AV  = BM * 4 / 256;     // vec16 per thread per A tile
    constexpr int ARS = 80;               // smem row stride (bytes)
    constexpr int T_AH = 0;
    constexpr int T_AL = BM * ARS;
    constexpr int T_WH = 2 * BM * ARS;
    constexpr int T_WL = 2 * BM * ARS + 128 * ARS;
    constexpr int STAGE = (2 * BM + 256) * ARS;

    extern __shared__ __align__(128) unsigned char smem[];
    const uint32_t smem_u = smem_u32(smem);

    const int tid  = threadIdx.x;
    const int wid  = tid >> 5;
    const int lane = tid & 31;
    const int warp_m = wid % NWM;
    const int warp_n = wid / NWM;
    const int m0 = blockIdx.y * BM;
    const int n0 = blockIdx.x * 128;

    // ldmatrix per-lane offsets relative to tile base
    const int quad = lane >> 3, liq = lane & 7;
    const int khB = (quad >> 1) * 16;
    uint32_t aOff[2], bOff[NAT / 2];
#pragma unroll
    for (int ma = 0; ma < 2; ma++) {
        int r = warp_m * 32 + ma * 16 + (quad & 1) * 8 + liq;
        aOff[ma] = r * ARS + khB;
    }
#pragma unroll
    for (int p = 0; p < NAT / 2; p++) {
        int r = warp_n * WNW + p * 16 + (quad & 1) * 8 + liq;
        bOff[p] = r * ARS + khB;
    }

    // cp.async coords
    int a_row[AV], a_c16[AV];
#pragma unroll
    for (int i = 0; i < AV; i++) {
        int v = tid + i * 256;
        a_row[i] = v >> 2; a_c16[i] = v & 3;
    }
    int b_row[2], b_c16[2];
#pragma unroll
    for (int i = 0; i < 2; i++) {
        int v = tid + i * 256;
        b_row[i] = v >> 2; b_c16[i] = v & 3;
    }

    float acc[2][NAT][4];
#pragma unroll
    for (int ma = 0; ma < 2; ma++)
#pragma unroll
        for (int na = 0; na < NAT; na++)
#pragma unroll
            for (int j = 0; j < 4; j++) acc[ma][na][j] = 0.f;

    const int chunksPerK = K / 32;
    const int total = (MODE == 0) ? chunksPerK : 2 * chunksPerK;

    auto issue_stage = [&](int c, int s) {
        const int dir = (MODE == 0) ? blockIdx.z : (c / chunksPerK);
        const int kc = (c % chunksPerK) * 32;
        const bf16* AhP = Ah + (size_t)dir * aDirStride;
        const bf16* AlP = Al + (size_t)dir * aDirStride;
        const bf16* WhP = Wh + (size_t)dir * wDirStride;
        const bf16* WlP = Wl + (size_t)dir * wDirStride;
        const bool flip = (dir == 1);
        const uint32_t base = smem_u + s * STAGE;
#pragma unroll
        for (int i = 0; i < AV; i++) {
            int m = m0 + a_row[i];
            int row = flip ? fliprow(m) : m;
            size_t go = (size_t)row * K + kc + a_c16[i] * 8;
            uint32_t so = a_row[i] * ARS + a_c16[i] * 16;
            cp_async16(base + T_AH + so, AhP + go);
            cp_async16(base + T_AL + so, AlP + go);
        }
#pragma unroll
        for (int i = 0; i < 2; i++) {
            size_t go = (size_t)(n0 + b_row[i]) * K + kc + b_c16[i] * 8;
            uint32_t so = b_row[i] * ARS + b_c16[i] * 16;
            cp_async16(base + T_WH + so, WhP + go);
            cp_async16(base + T_WL + so, WlP + go);
        }
        cp_commit();
    };

    issue_stage(0, 0);

    for (int c = 0; c < total; c++) {
        if (c + 1 < total) { issue_stage(c + 1, (c + 1) & 1); cp_wait<1>(); }
        else               { cp_wait<0>(); }
        __syncthreads();

        const uint32_t sbase = smem_u + (c & 1) * STAGE;
#pragma unroll
        for (int ks = 0; ks < 2; ks++) {
            const int ko = ks * 32;
            uint32_t ah[2][4], al[2][4];
            ldmx4(ah[0], sbase + T_AH + aOff[0] + ko);
            ldmx4(ah[1], sbase + T_AH + aOff[1] + ko);
            ldmx4(al[0], sbase + T_AL + aOff[0] + ko);
            ldmx4(al[1], sbase + T_AL + aOff[1] + ko);
            uint32_t bh[NAT][2], bl[NAT][2];
#pragma unroll
            for (int p = 0; p < NAT / 2; p++) {
                uint32_t r[4];
                ldmx4(r, sbase + T_WH + bOff[p] + ko);
                bh[2*p][0] = r[0]; bh[2*p][1] = r[2];
                bh[2*p+1][0] = r[1]; bh[2*p+1][1] = r[3];
                ldmx4(r, sbase + T_WL + bOff[p] + ko);
                bl[2*p][0] = r[0]; bl[2*p][1] = r[2];
                bl[2*p+1][0] = r[1]; bl[2*p+1][1] = r[3];
            }
#pragma unroll
            for (int ma = 0; ma < 2; ma++)
#pragma unroll
                for (int na = 0; na < NAT; na++) {
                    mma16816(acc[ma][na], ah[ma], bh[na]);
                    mma16816(acc[ma][na], al[ma], bh[na]);
                    mma16816(acc[ma][na], ah[ma], bl[na]);
                }
        }
        __syncthreads();
    }

    // epilogue
    float* Cd = C + ((MODE == 0) ? (size_t)blockIdx.z * cDirStride : 0);
#pragma unroll
    for (int ma = 0; ma < 2; ma++) {
#pragma unroll
        for (int na = 0; na < NAT; na++) {
            int row = m0 + warp_m * 32 + ma * 16 + (lane >> 2);
            int col = n0 + warp_n * WNW + na * 8 + 2 * (lane & 3);
            float2 v0 = make_float2(acc[ma][na][0], acc[ma][na][1]);
            float2 v1 = make_float2(acc[ma][na][2], acc[ma][na][3]);
            if (MODE == 1) {
                float2 x0 = *(const float2*)&X[(size_t)row * ldc + col];
                float2 x1 = *(const float2*)&X[(size_t)(row + 8) * ldc + col];
                v0.x += x0.x; v0.y += x0.y; v1.x += x1.x; v1.y += x1.y;
            }
            *(float2*)&Cd[(size_t)row * ldc + col] = v0;
            *(float2*)&Cd[(size_t)(row + 8) * ldc + col] = v1;
        }
    }
}

// ==================== fused hi/lo split prep (all tensors in one launch) ====================
struct SplitArgs {
    const float* src[5];
    bf16* hi[5];
    bf16* lo[5];
    int n4[5];
};

__global__ void split_all_kernel(SplitArgs a)
{
    const int r = blockIdx.y;
    int i = blockIdx.x * blockDim.x + threadIdx.x;
    if (i >= a.n4[r]) return;
    float4 v = ((const float4*)a.src[r])[i];
    bf16 h0 = __float2bfloat16(v.x), h1 = __float2bfloat16(v.y);
    bf16 h2 = __float2bfloat16(v.z), h3 = __float2bfloat16(v.w);
    bf16 l0 = __float2bfloat16(v.x - __bfloat162float(h0));
    bf16 l1 = __float2bfloat16(v.y - __bfloat162float(h1));
    bf16 l2 = __float2bfloat16(v.z - __bfloat162float(h2));
    bf16 l3 = __float2bfloat16(v.w - __bfloat162float(h3));
    ((__nv_bfloat162*)a.hi[r])[2*i]   = __nv_bfloat162(h0, h1);
    ((__nv_bfloat162*)a.hi[r])[2*i+1] = __nv_bfloat162(h2, h3);
    ((__nv_bfloat162*)a.lo[r])[2*i]   = __nv_bfloat162(l0, l1);
    ((__nv_bfloat162*)a.lo[r])[2*i+1] = __nv_bfloat162(l2, l3);
}

// ==================== SIMT GEMM for dt (K=48) ====================
template<int BM, int BN, int BK, int TM, int TN>
__global__ void __launch_bounds__((BM/TM)*(BN/TN), 2)
gemm_dt(const float* __restrict__ A, int lda, size_t aStride,
        const float* __restrict__ W0, const float* __restrict__ W1,
        float* __restrict__ C, int ldc, size_t cStride,
        int M, int N, int K,
        const float* __restrict__ bias0, const float* __restrict__ bias1)
{
    constexpr int THREADS = (BM/TM)*(BN/TN);
    constexpr int AF4 = BM*BK/4/THREADS;
    constexpr int BF4 = BN*BK/4/THREADS;
    __shared__ float As[BK][BM+4];
    __shared__ float Bs[BK][BN+4];

    const int tid = threadIdx.x;
    const int tx  = tid % (BN/TN);
    const int ty  = tid / (BN/TN);
    const int m0  = blockIdx.y * BM;
    const int n0  = blockIdx.x * BN;
    const int dir = blockIdx.z;

    const float* Ab = A + (size_t)dir * aStride;
    const float* W  = dir ? W1 : W0;
    const float* bias = dir ? bias1 : bias0;
    float* Cb = C + (size_t)dir * cStride;

    int a_mm[AF4], a_kk[AF4]; const float* a_ptr[AF4];
#pragma unroll
    for (int i = 0; i < AF4; i++) {
        int idx = tid + i * THREADS;
        a_mm[i] = idx / (BK/4); a_kk[i] = (idx % (BK/4)) * 4;
        a_ptr[i] = Ab + (size_t)(m0 + a_mm[i]) * lda + a_kk[i];
    }
    int b_nn[BF4], b_kk[BF4]; const float* b_ptr[BF4];
#pragma unroll
    for (int i = 0; i < BF4; i++) {
        int idx = tid + i * THREADS;
        b_nn[i] = idx / (BK/4); b_kk[i] = (idx % (BK/4)) * 4;
        b_ptr[i] = W + (size_t)(n0 + b_nn[i]) * K + b_kk[i];
    }

    float acc[TM][TN];
#pragma unroll
    for (int i = 0; i < TM; i++)
#pragma unroll
        for (int j = 0; j < TN; j++) acc[i][j] = 0.f;

    for (int k0 = 0; k0 < K; k0 += BK) {
#pragma unroll
        for (int i = 0; i < AF4; i++) {
            float4 v = *(const float4*)(a_ptr[i] + k0);
            As[a_kk[i]+0][a_mm[i]] = v.x; As[a_kk[i]+1][a_mm[i]] = v.y;
            As[a_kk[i]+2][a_mm[i]] = v.z; As[a_kk[i]+3][a_mm[i]] = v.w;
        }
#pragma unroll
        for (int i = 0; i < BF4; i++) {
            float4 v = *(const float4*)(b_ptr[i] + k0);
            Bs[b_kk[i]+0][b_nn[i]] = v.x; Bs[b_kk[i]+1][b_nn[i]] = v.y;
            Bs[b_kk[i]+2][b_nn[i]] = v.z; Bs[b_kk[i]+3][b_nn[i]] = v.w;
        }
        __syncthreads();
#pragma unroll
        for (int kk = 0; kk < BK; kk++) {
            float a[TM], b[TN];
#pragma unroll
            for (int i = 0; i < TM; i += 4) {
                float4 v = *(const float4*)&As[kk][ty*TM + i];
                a[i] = v.x; a[i+1] = v.y; a[i+2] = v.z; a[i+3] = v.w;
            }
#pragma unroll
            for (int j = 0; j < TN; j += 4) {
                float4 v = *(const float4*)&Bs[kk][tx*TN + j];
                b[j] = v.x; b[j+1] = v.y; b[j+2] = v.z; b[j+3] = v.w;
            }
#pragma unroll
            for (int i = 0; i < TM; i++)
#pragma unroll
                for (int j = 0; j < TN; j++) acc[i][j] += a[i] * b[j];
        }
        __syncthreads();
    }

#pragma unroll
    for (int i = 0; i < TM; i++) {
        int m = m0 + ty*TM + i;
#pragma unroll
        for (int j = 0; j < TN; j += 4) {
            int n = n0 + tx*TN + j;
            float4 v = make_float4(acc[i][j], acc[i][j+1], acc[i][j+2], acc[i][j+3]);
            v.x += bias[n+0]; v.y += bias[n+1]; v.z += bias[n+2]; v.w += bias[n+3];
            v.x = (v.x > 20.f) ? v.x : log1pf(expf(v.x));
            v.y = (v.y > 20.f) ? v.y : log1pf(expf(v.y));
            v.z = (v.z > 20.f) ? v.z : log1pf(expf(v.z));
            v.w = (v.w > 20.f) ? v.w : log1pf(expf(v.w));
            *(float4*)&Cb[(size_t)m * ldc + n] = v;
        }
    }
}

// ==================== x_dbl split-K ====================
__global__ void __launch_bounds__(256, 2)
xdbl_kernel(const float* __restrict__ Wx0, const float* __restrict__ Wx1)
{
    constexpr int BM = 128, BK = 16, KC = DI / XS;
    __shared__ float As[BK][BM+4];
    __shared__ float Bs[BK][NX+4];

    const int tid = threadIdx.x;
    const int tx  = tid % 16;
    const int ty  = tid / 16;
    const int m0    = blockIdx.x * BM;
    const int split = blockIdx.y;
    const int dir   = blockIdx.z;

    const float* A = g_xc + (size_t)dir * BB*LL*DI;
    const float* W = dir ? Wx1 : Wx0;
    const int kbase = split * KC;

    float acc[8][5];
#pragma unroll
    for (int i = 0; i < 8; i++)
#pragma unroll
        for (int j = 0; j < 5; j++) acc[i][j] = 0.f;

    for (int k0 = kbase; k0 < kbase + KC; k0 += BK) {
#pragma unroll
        for (int i = 0; i < 2; i++) {
            int idx = tid + i * 256;
            int mm = idx / 4, kk = (idx % 4) * 4;
            float4 v = *(const float4*)&A[(size_t)(m0+mm) * DI + k0 + kk];
            As[kk+0][mm] = v.x; As[kk+1][mm] = v.y; As[kk+2][mm] = v.z; As[kk+3][mm] = v.w;
        }
        for (int i = tid; i < NX * BK; i += 256) {
            int nn = i / BK, kk = i % BK;
            Bs[kk][nn] = W[(size_t)nn * DI + k0 + kk];
        }
        __syncthreads();
#pragma unroll
        for (int kk = 0; kk < BK; kk++) {
            float a[8], b[5];
#pragma unroll
            for (int i = 0; i < 8; i += 4) {
                float4 v = *(const float4*)&As[kk][ty*8 + i];
                a[i] = v.x; a[i+1] = v.y; a[i+2] = v.z; a[i+3] = v.w;
            }
#pragma unroll
            for (int j = 0; j < 5; j++) b[j] = Bs[kk][tx*5 + j];
#pragma unroll
            for (int i = 0; i < 8; i++)
#pragma unroll
                for (int j = 0; j < 5; j++) acc[i][j] += a[i] * b[j];
        }
        __syncthreads();
    }

    float* P = g_xdblp + ((size_t)split * 2 * BB * LL + (size_t)dir * BB * LL) * NX;
#pragma unroll
    for (int i = 0; i < 8; i++) {
        int m = m0 + ty*8 + i;
#pragma unroll
        for (int j = 0; j < 5; j++)
            P[(size_t)m * NX + tx*5 + j] = acc[i][j];
    }
}

__global__ void xdbl_reduce_kernel()
{
    const int N4 = 2 * BB * LL * NX / 4;
    int i = blockIdx.x * blockDim.x + threadIdx.x;
    if (i >= N4) return;
    const float4* P = (const float4*)g_xdblp;
    float4 s = P[i];
#pragma unroll
    for (int p = 1; p < XS; p++) {
        float4 v = P[(size_t)p * N4 + i];
        s.x += v.x; s.y += v.y; s.z += v.z; s.w += v.w;
    }
    ((float4*)g_xdbl)[i] = s;
}

// ==================== conv + silu ====================
__global__ void conv_silu_kernel(const float* __restrict__ cw_f, const float* __restrict__ cb_f,
                                 const float* __restrict__ cw_b, const float* __restrict__ cb_b)
{
    const int TOT4 = 2 * BB * LL * DI / 4;
    int idx = blockIdx.x * blockDim.x + threadIdx.x;
    if (idx >= TOT4) return;
    const int DQ = DI / 4;
    int dq = idx % DQ;
    int r = idx / DQ;
    int t = r % LL; r /= LL;
    int b = r % BB;
    int dir = r / BB;
    int d4 = dq * 4;
    const float* w  = dir ? cw_b : cw_f;
    const float* cb = dir ? cb_b : cb_f;
    const float* xp = g_xz + ((size_t)(dir * BB + b)) * LL * 2 * DI;

    float4 wr0 = *(const float4*)&w[(d4+0)*4];
    float4 wr1 = *(const float4*)&w[(d4+1)*4];
    float4 wr2 = *(const float4*)&w[(d4+2)*4];
    float4 wr3 = *(const float4*)&w[(d4+3)*4];
    float4 s = *(const float4*)&cb[d4];
#pragma unroll
    for (int k = 0; k < 4; k++) {
        int tt = t + k - 3;
        if (tt >= 0) {
            float4 xv = *(const float4*)&xp[(size_t)tt * 2 * DI + d4];
            s.x += ((const float*)&wr0)[k] * xv.x;
            s.y += ((const float*)&wr1)[k] * xv.y;
            s.z += ((const float*)&wr2)[k] * xv.z;
            s.w += ((const float*)&wr3)[k] * xv.w;
        }
    }
    s.x = s.x / (1.f + __expf(-s.x));
    s.y = s.y / (1.f + __expf(-s.y));
    s.z = s.z / (1.f + __expf(-s.z));
    s.w = s.w / (1.f + __expf(-s.w));
    ((float4*)g_xc)[idx] = s;
}

// ==================== selective scan (smem time-tiled) ====================
__global__ void __launch_bounds__(256)
scan_kernel(const float* __restrict__ Alog_f, const float* __restrict__ D_f,
            const float* __restrict__ Alog_b, const float* __restrict__ D_b)
{
    __shared__ float s_dt[TT][32], s_xc[TT][32], s_z[TT][32], s_bc[TT][32];
    __shared__ bf16  s_yh[TT][32], s_yl[TT][32];

    const int tid = threadIdx.x;
    const int s4 = tid & 7;
    const int dl = tid >> 3;
    const int d0  = blockIdx.x * 32;
    const int b   = blockIdx.y;
    const int dir = blockIdx.z;

    const float* Alog = dir ? Alog_b : Alog_f;
    const float* Dp   = dir ? D_b   : D_f;

    const size_t base_di = ((size_t)(dir * BB + b)) * LL * DI;
    const size_t base_x  = ((size_t)(dir * BB + b)) * LL * NX;
    const size_t base_z  = ((size_t)(dir * BB + b)) * LL * 2 * DI + DI;

    float2 Av = *(const float2*)&Alog[(d0 + dl) * DS + 2*s4];
    const float A0 = -__expf(Av.x);
    const float A1 = -__expf(Av.y);
    const float Dv = Dp[d0 + dl];

    float h0 = 0.f, h1 = 0.f;

    for (int t0 = 0; t0 < LL; t0 += TT) {
#pragma unroll
        for (int i = tid; i < TT * 32; i += 256) {
            int t = i >> 5, d = i & 31;
            size_t r = base_di + (size_t)(t0 + t) * DI + d0 + d;
            s_dt[t][d] = g_dt[r];
            s_xc[t][d] = g_xc[r];
            s_z [t][d] = g_xz[base_z + (size_t)(t0 + t) * 2 * DI + d0 + d];
            s_bc[t][d] = g_xdbl[base_x + (size_t)(t0 + t) * NX + DTR + d];
        }
        __syncthreads();

#pragma unroll 8
        for (int t = 0; t < TT; t++) {
            float dtv = s_dt[t][dl];
            float xcv = s_xc[t][dl];
            float B0 = s_bc[t][2*s4],      B1 = s_bc[t][2*s4 + 1];
            float C0 = s_bc[t][16 + 2*s4], C1 = s_bc[t][17 + 2*s4];
            float dx  = dtv * xcv;
            h0 = __expf(dtv * A0) * h0 + dx * B0;
            h1 = __expf(dtv * A1) * h1 + dx * B1;
            float p = h0 * C0 + h1 * C1;
            p += __shfl_xor_sync(0xffffffffu, p, 4);
            p += __shfl_xor_sync(0xffffffffu, p, 2);
            p += __shfl_xor_sync(0xffffffffu, p, 1);
            if (s4 == 0) {
                float zv = s_z[t][dl];
                float y = p + xcv * Dv;
                float sig = 1.f / (1.f + __expf(-zv));
                y = y * (zv * sig);
                bf16 h = __float2bfloat16(y);
                s_yh[t][dl] = h;
                s_yl[t][dl] = __float2bfloat16(y - __bfloat162float(h));
            }
        }
        __syncthreads();

#pragma unroll
        for (int i = tid; i < TT * 32; i += 256) {
            int t = i >> 5, d = i & 31;
            size_t r = base_di + (size_t)(t0 + t) * DI + d0 + d;
            g_y_h[r] = s_yh[t][d];
            g_y_l[r] = s_yl[t][d];
        }
        __syncthreads();
    }
}

static inline int cdiv(int a, int b) { return (a + b - 1) / b; }

extern "C" void kernel_launch(void* const* d_in, const int* in_sizes, int n_in,
                              void* d_out, int out_size)
{
    const float* x = (const float*)d_in[0];
    const float* W_in[2]   = { (const float*)d_in[1],  (const float*)d_in[10] };
    const float* conv_w[2] = { (const float*)d_in[2],  (const float*)d_in[11] };
    const float* conv_b[2] = { (const float*)d_in[3],  (const float*)d_in[12] };
    const float* W_x[2]    = { (const float*)d_in[4],  (const float*)d_in[13] };
    const float* W_dt[2]   = { (const float*)d_in[5],  (const float*)d_in[14] };
    const float* b_dt[2]   = { (const float*)d_in[6],  (const float*)d_in[15] };
    const float* A_log[2]  = { (const float*)d_in[7],  (const float*)d_in[16] };
    const float* Dvec[2]   = { (const float*)d_in[8],  (const float*)d_in[17] };
    const float* W_out[2]  = { (const float*)d_in[9],  (const float*)d_in[18] };
    float* out = (float*)d_out;

    float *p_xz, *p_xdbl, *p_dt;
    cudaGetSymbolAddress((void**)&p_xz,   g_xz);
    cudaGetSymbolAddress((void**)&p_xdbl, g_xdbl);
    cudaGetSymbolAddress((void**)&p_dt,   g_dt);
    bf16 *p_xh, *p_xl, *p_winh, *p_winl, *p_wouth, *p_woutl, *p_yh, *p_yl;
    cudaGetSymbolAddress((void**)&p_xh,    g_x_h);
    cudaGetSymbolAddress((void**)&p_xl,    g_x_l);
    cudaGetSymbolAddress((void**)&p_winh,  g_win_h);
    cudaGetSymbolAddress((void**)&p_winl,  g_win_l);
    cudaGetSymbolAddress((void**)&p_wouth, g_wout_h);
    cudaGetSymbolAddress((void**)&p_woutl, g_wout_l);
    cudaGetSymbolAddress((void**)&p_yh,    g_y_h);
    cudaGetSymbolAddress((void**)&p_yl,    g_y_l);

    const int M = BB * LL;  // 2048

    const int SMEM_G0 = 2 * (2 * 128 + 256) * 80;   // 81920
    const int SMEM_G1 = 2 * (2 * 64 + 256) * 80;    // 61440
    cudaFuncSetAttribute(mma_gemm<0,128>, cudaFuncAttributeMaxDynamicSharedMemorySize, SMEM_G0);
    cudaFuncSetAttribute(mma_gemm<1,64>,  cudaFuncAttributeMaxDynamicSharedMemorySize, SMEM_G1);

    // 0) hi/lo splits of x and weights (one launch)
    {
        SplitArgs a;
        a.src[0] = x;        a.hi[0] = p_xh;    a.lo[0] = p_xl;    a.n4[0] = M * DIMM / 4;
        a.src[1] = W_in[0];  a.hi[1] = p_winh;  a.lo[1] = p_winl;  a.n4[1] = 2 * DI * DIMM / 4;
        a.src[2] = W_in[1];  a.hi[2] = p_winh + (size_t)2*DI*DIMM;
                             a.lo[2] = p_winl + (size_t)2*DI*DIMM; a.n4[2] = 2 * DI * DIMM / 4;
        a.src[3] = W_out[0]; a.hi[3] = p_wouth; a.lo[3] = p_woutl; a.n4[3] = DIMM * DI / 4;
        a.src[4] = W_out[1]; a.hi[4] = p_wouth + (size_t)DIMM*DI;
                             a.lo[4] = p_woutl + (size_t)DIMM*DI;  a.n4[4] = DIMM * DI / 4;
        int maxn4 = 2 * DI * DIMM / 4;
        dim3 grid(cdiv(maxn4, 256), 5);
        split_all_kernel<<<grid, 256>>>(a);
    }

    // 1) xz = x(+flip) @ W_in^T  (HMMA fused 3-product)
    {
        dim3 grid(2 * DI / 128, M / 128, 2);
        mma_gemm<0, 128><<<grid, 256, SMEM_G0>>>(
            p_xh, p_xl, p_winh, p_winl,
            p_xz, nullptr,
            DIMM, 2 * DI,
            0, (size_t)2*DI*DIMM, (size_t)M * 2 * DI);
    }

    // 2) conv + silu -> g_xc
    {
        int n4 = 2 * BB * LL * DI / 4;
        conv_silu_kernel<<<cdiv(n4, 256), 256>>>(conv_w[0], conv_b[0], conv_w[1], conv_b[1]);
    }

    // 3) x_dbl = xc @ W_x^T (split-K + reduce)
    {
        dim3 grid(M / 128, XS, 2);
        xdbl_kernel<<<grid, 256>>>(W_x[0], W_x[1]);
        int n4 = 2 * BB * LL * NX / 4;
        xdbl_reduce_kernel<<<cdiv(n4, 256), 256>>>();
    }

    // 4) dt = softplus(x_dbl[:, :48] @ W_dt^T + b_dt)
    {
        dim3 grid(DI / 128, M / 128, 2);
        gemm_dt<128,128,16,8,8><<<grid, 256>>>(
            p_xdbl, NX, (size_t)M * NX,
            W_dt[0], W_dt[1],
            p_dt, DI, (size_t)M * DI,
            M, DI, DTR, b_dt[0], b_dt[1]);
    }

    // 5) selective scan + gating -> y hi/lo
    {
        dim3 grid(DI / 32, BB, 2);
        scan_kernel<<<grid, 256>>>(A_log[0], Dvec[0], A_log[1], Dvec[1]);
    }

    // 6) out = x + y0 @ W0^T + flip(y1) @ W1^T  (HMMA fused 3-product)
    {
        dim3 grid(DIMM / 128, M / 64, 1);
        mma_gemm<1, 64><<<grid, 256, SMEM_G1>>>(
            p_yh, p_yl, p_wouth, p_woutl,
            out, x,
            DI, DIMM,
            (size_t)M * DI, (size_t)DIMM * DI, 0);
    }

    (void)in_sizes; (void)n_in; (void)out_size;
}